// round 1
// baseline (speedup 1.0000x reference)
#include <cuda_runtime.h>
#include <math.h>

// Problem constants
#define B_  2
#define L_  2048
#define D_  1024
#define H_  16
#define DH_ 64
#define NT  (B_*L_)          // 4096 tokens
#define ND  (B_*H_*L_*DH_)   // 4M elements per Q/K/V

// Scratch (device-global statics — allocation-free per harness rules)
__device__ float g_q[ND];
__device__ float g_k[ND];
__device__ float g_v[ND];
__device__ float g_ctx[NT * D_];
__device__ float g_y[NT * D_];

// ---------------------------------------------------------------------------
// GEMM 1: qkv = x @ W_in^T + b_in, scatter into Q/K/V [B,H,L,DH]
// M=4096, N=3072, K=1024. Both A and B are K-major (row-major, K contiguous).
// Tile 128x128x16, 256 threads, 8x8 microtile (split 4+4 to limit bank conflicts)
// ---------------------------------------------------------------------------
__global__ __launch_bounds__(256) void qkv_gemm_kernel(
    const float* __restrict__ A,     // x [4096,1024]
    const float* __restrict__ W,     // in_proj_w [3072,1024]
    const float* __restrict__ bias)  // [3072]
{
    __shared__ float As[16][132];
    __shared__ float Bs[16][132];
    const int bn = blockIdx.x, bm = blockIdx.y;
    const int tid = threadIdx.x;
    const int tx = tid & 15, ty = tid >> 4;

    float c[8][8];
#pragma unroll
    for (int i = 0; i < 8; i++)
#pragma unroll
        for (int j = 0; j < 8; j++) c[i][j] = 0.f;

    const float* Ab = A + (size_t)(bm * 128) * 1024;
    const float* Wb = W + (size_t)(bn * 128) * 1024;

    for (int k0 = 0; k0 < 1024; k0 += 16) {
#pragma unroll
        for (int i = 0; i < 2; i++) {
            int f = tid + i * 256;       // 0..511
            int row = f >> 2, k4 = f & 3;
            float4 va = *(const float4*)(Ab + (size_t)row * 1024 + k0 + k4 * 4);
            As[k4 * 4 + 0][row] = va.x;
            As[k4 * 4 + 1][row] = va.y;
            As[k4 * 4 + 2][row] = va.z;
            As[k4 * 4 + 3][row] = va.w;
            float4 vb = *(const float4*)(Wb + (size_t)row * 1024 + k0 + k4 * 4);
            Bs[k4 * 4 + 0][row] = vb.x;
            Bs[k4 * 4 + 1][row] = vb.y;
            Bs[k4 * 4 + 2][row] = vb.z;
            Bs[k4 * 4 + 3][row] = vb.w;
        }
        __syncthreads();
#pragma unroll
        for (int k = 0; k < 16; k++) {
            float a[8], b[8];
            *(float4*)(a)     = *(const float4*)&As[k][ty * 4];
            *(float4*)(a + 4) = *(const float4*)&As[k][64 + ty * 4];
            *(float4*)(b)     = *(const float4*)&Bs[k][tx * 4];
            *(float4*)(b + 4) = *(const float4*)&Bs[k][64 + tx * 4];
#pragma unroll
            for (int i = 0; i < 8; i++)
#pragma unroll
                for (int j = 0; j < 8; j++)
                    c[i][j] = fmaf(a[i], b[j], c[i][j]);
        }
        __syncthreads();
    }

    // Epilogue: scatter to Q/K/V in [B,H,L,DH]
#pragma unroll
    for (int i = 0; i < 8; i++) {
        int ri = bm * 128 + ((i < 4) ? (ty * 4 + i) : (64 + ty * 4 + (i - 4)));
        int bb = ri >> 11, l = ri & 2047;
#pragma unroll
        for (int j = 0; j < 8; j++) {
            int n = bn * 128 + ((j < 4) ? (tx * 4 + j) : (64 + tx * 4 + (j - 4)));
            float v = c[i][j] + bias[n];
            int part = n >> 10;          // uniform per block (128 | 1024)
            int hd = n & 1023;
            int h = hd >> 6, dh = hd & 63;
            size_t dst = ((size_t)(bb * H_ + h) * L_ + l) * DH_ + dh;
            if (part == 0)      g_q[dst] = v;
            else if (part == 1) g_k[dst] = v;
            else                g_v[dst] = v;
        }
    }
}

// ---------------------------------------------------------------------------
// Flash attention (fp32), per block: one (b,h), 64 query rows; stream keys in
// tiles of 64 with online softmax. Softmax is invariant to the per-batch
// "vol" constant, so market_info is dropped.
// ---------------------------------------------------------------------------
#define PITCH 65
__global__ __launch_bounds__(256) void attn_kernel()
{
    extern __shared__ float sm[];
    float* Qs   = sm;                      // 64*65
    float* Ks   = Qs + 64 * PITCH;         // 64*65
    float* Vs   = Ks + 64 * PITCH;         // 64*65
    float* Ss   = Vs + 64 * PITCH;         // 64*65 (scores then probs)
    float* m_sm = Ss + 64 * PITCH;         // 64
    float* l_sm = m_sm + 64;               // 64
    float* a_sm = l_sm + 64;               // 64

    const int bh = blockIdx.y;             // 0..31
    const int bb = bh >> 4, h = bh & 15;
    const int q0 = blockIdx.x * 64;
    const int tid = threadIdx.x;
    const int tr = tid >> 4, tc = tid & 15;

    const float* Qg = g_q + ((size_t)bh * L_ + q0) * DH_;
    const float* Kg = g_k + (size_t)bh * L_ * DH_;
    const float* Vg = g_v + (size_t)bh * L_ * DH_;

    // Load Q tile (64x64) into smem (pitch 65)
#pragma unroll
    for (int i = 0; i < 4; i++) {
        int f = tid + i * 256;             // 0..1023 float4s
        int r = f >> 4, c4 = f & 15;
        float4 v = *(const float4*)(Qg + (size_t)r * 64 + c4 * 4);
        float* d = Qs + r * PITCH + c4 * 4;
        d[0] = v.x; d[1] = v.y; d[2] = v.z; d[3] = v.w;
    }
    if (tid < 64) { m_sm[tid] = -1e30f; l_sm[tid] = 0.f; }

    float o[16];
#pragma unroll
    for (int i = 0; i < 16; i++) o[i] = 0.f;

    for (int kt = 0; kt < L_ / 64; kt++) {
        __syncthreads();   // previous iter phase C done reading Ks/Vs/Ss
        const float* Kt = Kg + (size_t)kt * 64 * 64;
        const float* Vt = Vg + (size_t)kt * 64 * 64;
#pragma unroll
        for (int i = 0; i < 4; i++) {
            int f = tid + i * 256;
            int r = f >> 4, c4 = f & 15;
            float4 kv = *(const float4*)(Kt + (size_t)r * 64 + c4 * 4);
            float* dk = Ks + r * PITCH + c4 * 4;
            dk[0] = kv.x; dk[1] = kv.y; dk[2] = kv.z; dk[3] = kv.w;
            float4 vv = *(const float4*)(Vt + (size_t)r * 64 + c4 * 4);
            float* dv = Vs + r * PITCH + c4 * 4;
            dv[0] = vv.x; dv[1] = vv.y; dv[2] = vv.z; dv[3] = vv.w;
        }
        __syncthreads();

        // Phase A: S = (Q @ K^T) * scale ; 4x4 microtile per thread
        {
            float acc[16];
#pragma unroll
            for (int i = 0; i < 16; i++) acc[i] = 0.f;
#pragma unroll
            for (int k = 0; k < 64; k++) {
                float a[4], b[4];
#pragma unroll
                for (int i = 0; i < 4; i++) a[i] = Qs[(tr * 4 + i) * PITCH + k];
#pragma unroll
                for (int j = 0; j < 4; j++) b[j] = Ks[(tc * 4 + j) * PITCH + k];
#pragma unroll
                for (int i = 0; i < 4; i++)
#pragma unroll
                    for (int j = 0; j < 4; j++)
                        acc[i * 4 + j] = fmaf(a[i], b[j], acc[i * 4 + j]);
            }
#pragma unroll
            for (int i = 0; i < 4; i++)
#pragma unroll
                for (int j = 0; j < 4; j++)
                    Ss[(tr * 4 + i) * PITCH + tc * 4 + j] = acc[i * 4 + j] * 0.125f;
        }
        __syncthreads();

        // Phase B: online softmax row update (4 threads per row)
        {
            int row = tid >> 2, sub = tid & 3;
            float* srow = Ss + row * PITCH + sub * 16;
            float mx = -1e30f;
#pragma unroll
            for (int t = 0; t < 16; t++) mx = fmaxf(mx, srow[t]);
            mx = fmaxf(mx, __shfl_xor_sync(0xffffffffu, mx, 1));
            mx = fmaxf(mx, __shfl_xor_sync(0xffffffffu, mx, 2));
            float m_old = m_sm[row];
            float m_new = fmaxf(m_old, mx);
            float alpha = __expf(m_old - m_new);
            float lsum = 0.f;
#pragma unroll
            for (int t = 0; t < 16; t++) {
                float p = __expf(srow[t] - m_new);
                srow[t] = p;
                lsum += p;
            }
            lsum += __shfl_xor_sync(0xffffffffu, lsum, 1);
            lsum += __shfl_xor_sync(0xffffffffu, lsum, 2);
            if (sub == 0) {
                l_sm[row] = l_sm[row] * alpha + lsum;
                m_sm[row] = m_new;
                a_sm[row] = alpha;
            }
        }
        __syncthreads();

        // Phase C: O = alpha*O + P @ V
        {
            float al[4];
#pragma unroll
            for (int i = 0; i < 4; i++) al[i] = a_sm[tr * 4 + i];
#pragma unroll
            for (int i = 0; i < 4; i++)
#pragma unroll
                for (int j = 0; j < 4; j++)
                    o[i * 4 + j] *= al[i];
#pragma unroll
            for (int k = 0; k < 64; k++) {
                float p[4], v[4];
#pragma unroll
                for (int i = 0; i < 4; i++) p[i] = Ss[(tr * 4 + i) * PITCH + k];
#pragma unroll
                for (int j = 0; j < 4; j++) v[j] = Vs[k * PITCH + tc * 4 + j];
#pragma unroll
                for (int i = 0; i < 4; i++)
#pragma unroll
                    for (int j = 0; j < 4; j++)
                        o[i * 4 + j] = fmaf(p[i], v[j], o[i * 4 + j]);
            }
        }
    }
    __syncthreads();

    // Write ctx in [B,L,H,DH] == row-major (token, D)
#pragma unroll
    for (int i = 0; i < 4; i++) {
        int row = tr * 4 + i;
        float inv = 1.0f / l_sm[row];
        int ql = q0 + row;
        float* dst = g_ctx + ((size_t)(bb * L_ + ql) * H_ + h) * DH_ + tc * 4;
#pragma unroll
        for (int j = 0; j < 4; j++) dst[j] = o[i * 4 + j] * inv;
    }
}

// ---------------------------------------------------------------------------
// GEMM 2: y = x + ctx @ W_out^T + b_out  (M=4096, N=1024, K=1024)
// ---------------------------------------------------------------------------
__global__ __launch_bounds__(256) void out_gemm_kernel(
    const float* __restrict__ X,     // x [4096,1024] residual
    const float* __restrict__ W,     // out_proj_w [1024,1024]
    const float* __restrict__ bias)  // [1024]
{
    __shared__ float As[16][132];
    __shared__ float Bs[16][132];
    const int bn = blockIdx.x, bm = blockIdx.y;
    const int tid = threadIdx.x;
    const int tx = tid & 15, ty = tid >> 4;

    float c[8][8];
#pragma unroll
    for (int i = 0; i < 8; i++)
#pragma unroll
        for (int j = 0; j < 8; j++) c[i][j] = 0.f;

    const float* Ab = g_ctx + (size_t)(bm * 128) * 1024;
    const float* Wb = W + (size_t)(bn * 128) * 1024;

    for (int k0 = 0; k0 < 1024; k0 += 16) {
#pragma unroll
        for (int i = 0; i < 2; i++) {
            int f = tid + i * 256;
            int row = f >> 2, k4 = f & 3;
            float4 va = *(const float4*)(Ab + (size_t)row * 1024 + k0 + k4 * 4);
            As[k4 * 4 + 0][row] = va.x;
            As[k4 * 4 + 1][row] = va.y;
            As[k4 * 4 + 2][row] = va.z;
            As[k4 * 4 + 3][row] = va.w;
            float4 vb = *(const float4*)(Wb + (size_t)row * 1024 + k0 + k4 * 4);
            Bs[k4 * 4 + 0][row] = vb.x;
            Bs[k4 * 4 + 1][row] = vb.y;
            Bs[k4 * 4 + 2][row] = vb.z;
            Bs[k4 * 4 + 3][row] = vb.w;
        }
        __syncthreads();
#pragma unroll
        for (int k = 0; k < 16; k++) {
            float a[8], b[8];
            *(float4*)(a)     = *(const float4*)&As[k][ty * 4];
            *(float4*)(a + 4) = *(const float4*)&As[k][64 + ty * 4];
            *(float4*)(b)     = *(const float4*)&Bs[k][tx * 4];
            *(float4*)(b + 4) = *(const float4*)&Bs[k][64 + tx * 4];
#pragma unroll
            for (int i = 0; i < 8; i++)
#pragma unroll
                for (int j = 0; j < 8; j++)
                    c[i][j] = fmaf(a[i], b[j], c[i][j]);
        }
        __syncthreads();
    }

#pragma unroll
    for (int i = 0; i < 8; i++) {
        int ri = bm * 128 + ((i < 4) ? (ty * 4 + i) : (64 + ty * 4 + (i - 4)));
#pragma unroll
        for (int j = 0; j < 8; j++) {
            int n = bn * 128 + ((j < 4) ? (tx * 4 + j) : (64 + tx * 4 + (j - 4)));
            g_y[(size_t)ri * 1024 + n] = c[i][j] + bias[n] + X[(size_t)ri * 1024 + n];
        }
    }
}

// ---------------------------------------------------------------------------
// LayerNorm over last dim (1024), one block per token row
// ---------------------------------------------------------------------------
__global__ __launch_bounds__(256) void ln_kernel(
    const float* __restrict__ gamma,
    const float* __restrict__ beta,
    float* __restrict__ out)
{
    const int row = blockIdx.x;
    const float* yr = g_y + (size_t)row * 1024;
    const int tid = threadIdx.x;

    float s = 0.f, sq = 0.f;
#pragma unroll
    for (int i = tid; i < 1024; i += 256) {
        float v = yr[i];
        s += v;
        sq += v * v;
    }
#pragma unroll
    for (int off = 16; off > 0; off >>= 1) {
        s  += __shfl_xor_sync(0xffffffffu, s, off);
        sq += __shfl_xor_sync(0xffffffffu, sq, off);
    }
    __shared__ float ws[8], wq[8];
    __shared__ float mu_s, rstd_s;
    int w = tid >> 5;
    if ((tid & 31) == 0) { ws[w] = s; wq[w] = sq; }
    __syncthreads();
    if (tid == 0) {
        float S = 0.f, Q = 0.f;
#pragma unroll
        for (int i = 0; i < 8; i++) { S += ws[i]; Q += wq[i]; }
        float mu = S * (1.0f / 1024.0f);
        float var = Q * (1.0f / 1024.0f) - mu * mu;
        mu_s = mu;
        rstd_s = rsqrtf(var + 1e-5f);
    }
    __syncthreads();
    float mu = mu_s, rstd = rstd_s;
#pragma unroll
    for (int i = tid; i < 1024; i += 256) {
        out[(size_t)row * 1024 + i] = (yr[i] - mu) * rstd * gamma[i] + beta[i];
    }
}

// ---------------------------------------------------------------------------
extern "C" void kernel_launch(void* const* d_in, const int* in_sizes, int n_in,
                              void* d_out, int out_size)
{
    const float* x      = (const float*)d_in[0];
    // d_in[1] = market_info: softmax-invariant constant, unused
    const float* w_in   = (const float*)d_in[2];
    const float* b_in   = (const float*)d_in[3];
    const float* w_out  = (const float*)d_in[4];
    const float* b_out  = (const float*)d_in[5];
    const float* gamma  = (const float*)d_in[6];
    const float* beta   = (const float*)d_in[7];
    float* out = (float*)d_out;

    // QKV projection
    qkv_gemm_kernel<<<dim3(24, 32), 256>>>(x, w_in, b_in);

    // Attention (67.3 KB dynamic smem)
    const int attn_smem = (4 * 64 * PITCH + 3 * 64) * (int)sizeof(float);
    cudaFuncSetAttribute(attn_kernel, cudaFuncAttributeMaxDynamicSharedMemorySize,
                         attn_smem);
    attn_kernel<<<dim3(L_ / 64, B_ * H_), 256, attn_smem>>>();

    // Output projection + residual
    out_gemm_kernel<<<dim3(8, 32), 256>>>(x, w_out, b_out);

    // LayerNorm
    ln_kernel<<<NT, 256>>>(gamma, beta, out);
}

// round 5
// speedup vs baseline: 2.1875x; 2.1875x over previous
#include <cuda_runtime.h>
#include <math.h>

// Problem constants
#define B_  2
#define L_  2048
#define D_  1024
#define H_  16
#define DH_ 64
#define NT  (B_*L_)          // 4096 tokens
#define ND  (B_*H_*L_*DH_)   // 4M elements per Q/K/V

typedef unsigned int uint;

// Scratch (device-global statics). Q/K/V/ctx hold tf32 bit patterns (uint).
__device__ uint  g_q[ND];
__device__ uint  g_k[ND];
__device__ uint  g_v[ND];
__device__ uint  g_ctx[NT * D_];
__device__ float g_y[NT * D_];

// ---------------------------------------------------------------------------
// tf32 helpers
// ---------------------------------------------------------------------------
__device__ __forceinline__ uint f2tf(float f) {
    uint u;
    asm("cvt.rna.tf32.f32 %0, %1;" : "=r"(u) : "f"(f));
    return u;
}

__device__ __forceinline__ void mma_tf32(
    float& c0, float& c1, float& c2, float& c3,
    uint a0, uint a1, uint a2, uint a3, uint b0, uint b1)
{
    asm volatile(
        "mma.sync.aligned.m16n8k8.row.col.f32.tf32.tf32.f32 "
        "{%0,%1,%2,%3}, {%4,%5,%6,%7}, {%8,%9}, {%0,%1,%2,%3};"
        : "+f"(c0), "+f"(c1), "+f"(c2), "+f"(c3)
        : "r"(a0), "r"(a1), "r"(a2), "r"(a3), "r"(b0), "r"(b1));
}

// ---------------------------------------------------------------------------
// GEMM 1: qkv = x @ W_in^T + b_in  (M=4096, N=3072, K=1024), tf32 MMA
// Block tile 128x128, k-tile 32, 8 warps (2m x 4n), warp tile 64x32.
// Epilogue scatters tf32 bits into Q/K/V [B,H,L,DH].
// ---------------------------------------------------------------------------
__global__ __launch_bounds__(256) void qkv_gemm_tf32(
    const float* __restrict__ A,     // x [4096,1024]
    const float* __restrict__ W,     // in_proj_w [3072,1024]
    const float* __restrict__ bias)  // [3072]
{
    __shared__ uint As[32][132];     // [k][m], tf32 bits
    __shared__ uint Bs[32][132];     // [k][n]
    const int bn = blockIdx.x, bm = blockIdx.y;
    const int tid = threadIdx.x;
    const int lane = tid & 31, wid = tid >> 5;
    const int wm = (wid & 1) * 64, wn = (wid >> 1) * 32;
    const int g = lane >> 2, c = lane & 3;

    float acc[4][4][4];
#pragma unroll
    for (int mf = 0; mf < 4; mf++)
#pragma unroll
        for (int nf = 0; nf < 4; nf++)
#pragma unroll
            for (int r = 0; r < 4; r++) acc[mf][nf][r] = 0.f;

    const float* Ab = A + (size_t)(bm * 128) * 1024;
    const float* Wb = W + (size_t)(bn * 128) * 1024;

    for (int k0 = 0; k0 < 1024; k0 += 32) {
        __syncthreads();
#pragma unroll
        for (int i = 0; i < 4; i++) {
            int f = tid + i * 256;          // 0..1023
            int m = f >> 3, kq = f & 7;
            float4 va = *(const float4*)(Ab + (size_t)m * 1024 + k0 + kq * 4);
            As[kq * 4 + 0][m] = f2tf(va.x);
            As[kq * 4 + 1][m] = f2tf(va.y);
            As[kq * 4 + 2][m] = f2tf(va.z);
            As[kq * 4 + 3][m] = f2tf(va.w);
            float4 vb = *(const float4*)(Wb + (size_t)m * 1024 + k0 + kq * 4);
            Bs[kq * 4 + 0][m] = f2tf(vb.x);
            Bs[kq * 4 + 1][m] = f2tf(vb.y);
            Bs[kq * 4 + 2][m] = f2tf(vb.z);
            Bs[kq * 4 + 3][m] = f2tf(vb.w);
        }
        __syncthreads();
#pragma unroll
        for (int ks = 0; ks < 4; ks++) {
            uint a[4][4], b[4][2];
#pragma unroll
            for (int mf = 0; mf < 4; mf++) {
                a[mf][0] = As[ks * 8 + c][wm + mf * 16 + g];
                a[mf][1] = As[ks * 8 + c][wm + mf * 16 + g + 8];
                a[mf][2] = As[ks * 8 + c + 4][wm + mf * 16 + g];
                a[mf][3] = As[ks * 8 + c + 4][wm + mf * 16 + g + 8];
            }
#pragma unroll
            for (int nf = 0; nf < 4; nf++) {
                b[nf][0] = Bs[ks * 8 + c][wn + nf * 8 + g];
                b[nf][1] = Bs[ks * 8 + c + 4][wn + nf * 8 + g];
            }
#pragma unroll
            for (int mf = 0; mf < 4; mf++)
#pragma unroll
                for (int nf = 0; nf < 4; nf++)
                    mma_tf32(acc[mf][nf][0], acc[mf][nf][1], acc[mf][nf][2], acc[mf][nf][3],
                             a[mf][0], a[mf][1], a[mf][2], a[mf][3],
                             b[nf][0], b[nf][1]);
        }
    }

    // Epilogue: scatter tf32 bits into Q/K/V [B,H,L,DH]
#pragma unroll
    for (int mf = 0; mf < 4; mf++) {
#pragma unroll
        for (int rr = 0; rr < 2; rr++) {          // row g / row g+8
            int ri = bm * 128 + wm + mf * 16 + g + rr * 8;
            int bb = ri >> 11, l = ri & 2047;
#pragma unroll
            for (int nf = 0; nf < 4; nf++) {
#pragma unroll
                for (int jj = 0; jj < 2; jj++) {
                    int n = bn * 128 + wn + nf * 8 + 2 * c + jj;
                    float v = acc[mf][nf][rr * 2 + jj] + bias[n];
                    int part = n >> 10;            // uniform per block
                    int hd = n & 1023;
                    int h = hd >> 6, dh = hd & 63;
                    size_t dst = ((size_t)(bb * H_ + h) * L_ + l) * DH_ + dh;
                    uint uv = f2tf(v);
                    if (part == 0)      g_q[dst] = uv;
                    else if (part == 1) g_k[dst] = uv;
                    else                g_v[dst] = uv;
                }
            }
        }
    }
}

// ---------------------------------------------------------------------------
// Flash attention with tf32 MMA. Block = one (b,h) x 64 q-rows, 4 warps.
// Each warp owns 16 q-rows end-to-end. Softmax in registers (4-lane shfl).
// Softmax is invariant to the per-batch "vol" constant -> market_info dropped.
// ---------------------------------------------------------------------------
#define AP 68   // smem pitch (uints)
__global__ __launch_bounds__(128) void attn_tf32()
{
    extern __shared__ uint sm[];
    uint* Qs = sm;                        // 64 x AP
    uint* Ks = Qs + 64 * AP;              // 64 x AP
    uint* Vs = Ks + 64 * AP;              // 64 x AP
    uint* Psw = Vs + 64 * AP;             // 4 warps x 16 x AP

    const int bh = blockIdx.y;            // 0..31
    const int bb = bh >> 4, h = bh & 15;
    const int q0 = blockIdx.x * 64;
    const int tid = threadIdx.x;
    const int lane = tid & 31, w = tid >> 5;
    const int g = lane >> 2, c = lane & 3;
    uint* Ps = Psw + w * 16 * AP;

    const uint* Qg = g_q + ((size_t)bh * L_ + q0) * DH_;
    const uint* Kg = g_k + (size_t)bh * L_ * DH_;
    const uint* Vg = g_v + (size_t)bh * L_ * DH_;

    // Load Q tile (64x64 tf32 bits)
#pragma unroll
    for (int i = 0; i < 8; i++) {
        int f = tid + i * 128;            // 0..1023 uint4s
        int r = f >> 4, c4 = f & 15;
        uint4 v = *(const uint4*)(Qg + (size_t)r * 64 + c4 * 4);
        uint* d = Qs + r * AP + c4 * 4;
        d[0] = v.x; d[1] = v.y; d[2] = v.z; d[3] = v.w;
    }

    float m0 = -1e30f, m1 = -1e30f, l0 = 0.f, l1 = 0.f;
    float o[8][4];
#pragma unroll
    for (int nf = 0; nf < 8; nf++)
#pragma unroll
        for (int r = 0; r < 4; r++) o[nf][r] = 0.f;

    for (int kt = 0; kt < L_ / 64; kt++) {
        __syncthreads();                  // prev iter reads of Ks/Vs/Ps done
        const uint* Kt = Kg + (size_t)kt * 64 * 64;
        const uint* Vt = Vg + (size_t)kt * 64 * 64;
#pragma unroll
        for (int i = 0; i < 8; i++) {
            int f = tid + i * 128;
            int r = f >> 4, c4 = f & 15;
            uint4 kv = *(const uint4*)(Kt + (size_t)r * 64 + c4 * 4);
            uint* dk = Ks + r * AP + c4 * 4;
            dk[0] = kv.x; dk[1] = kv.y; dk[2] = kv.z; dk[3] = kv.w;
            uint4 vv = *(const uint4*)(Vt + (size_t)r * 64 + c4 * 4);
            uint* dv = Vs + r * AP + c4 * 4;
            dv[0] = vv.x; dv[1] = vv.y; dv[2] = vv.z; dv[3] = vv.w;
        }
        __syncthreads();

        // --- S = Q @ K^T (warp tile 16 x 64) ---
        float s[8][4];
#pragma unroll
        for (int nf = 0; nf < 8; nf++)
#pragma unroll
            for (int r = 0; r < 4; r++) s[nf][r] = 0.f;
#pragma unroll
        for (int ks = 0; ks < 8; ks++) {
            uint a0 = Qs[(w * 16 + g) * AP + ks * 8 + c];
            uint a1 = Qs[(w * 16 + g + 8) * AP + ks * 8 + c];
            uint a2 = Qs[(w * 16 + g) * AP + ks * 8 + c + 4];
            uint a3 = Qs[(w * 16 + g + 8) * AP + ks * 8 + c + 4];
#pragma unroll
            for (int nf = 0; nf < 8; nf++) {
                uint b0 = Ks[(nf * 8 + g) * AP + ks * 8 + c];
                uint b1 = Ks[(nf * 8 + g) * AP + ks * 8 + c + 4];
                mma_tf32(s[nf][0], s[nf][1], s[nf][2], s[nf][3],
                         a0, a1, a2, a3, b0, b1);
            }
        }

        // --- online softmax (rows g and g+8 of this warp's 16) ---
        float mx0 = -1e30f, mx1 = -1e30f;
#pragma unroll
        for (int nf = 0; nf < 8; nf++) {
#pragma unroll
            for (int r = 0; r < 4; r++) s[nf][r] *= 0.125f;
            mx0 = fmaxf(mx0, fmaxf(s[nf][0], s[nf][1]));
            mx1 = fmaxf(mx1, fmaxf(s[nf][2], s[nf][3]));
        }
        mx0 = fmaxf(mx0, __shfl_xor_sync(0xffffffffu, mx0, 1));
        mx0 = fmaxf(mx0, __shfl_xor_sync(0xffffffffu, mx0, 2));
        mx1 = fmaxf(mx1, __shfl_xor_sync(0xffffffffu, mx1, 1));
        mx1 = fmaxf(mx1, __shfl_xor_sync(0xffffffffu, mx1, 2));
        float mn0 = fmaxf(m0, mx0), mn1 = fmaxf(m1, mx1);
        float al0 = __expf(m0 - mn0), al1 = __expf(m1 - mn1);
        float ls0 = 0.f, ls1 = 0.f;
#pragma unroll
        for (int nf = 0; nf < 8; nf++) {
            float p0 = __expf(s[nf][0] - mn0);
            float p1 = __expf(s[nf][1] - mn0);
            float p2 = __expf(s[nf][2] - mn1);
            float p3 = __expf(s[nf][3] - mn1);
            ls0 += p0 + p1;
            ls1 += p2 + p3;
            Ps[g * AP + nf * 8 + 2 * c]           = f2tf(p0);
            Ps[g * AP + nf * 8 + 2 * c + 1]       = f2tf(p1);
            Ps[(g + 8) * AP + nf * 8 + 2 * c]     = f2tf(p2);
            Ps[(g + 8) * AP + nf * 8 + 2 * c + 1] = f2tf(p3);
        }
        ls0 += __shfl_xor_sync(0xffffffffu, ls0, 1);
        ls0 += __shfl_xor_sync(0xffffffffu, ls0, 2);
        ls1 += __shfl_xor_sync(0xffffffffu, ls1, 1);
        ls1 += __shfl_xor_sync(0xffffffffu, ls1, 2);
        l0 = l0 * al0 + ls0; m0 = mn0;
        l1 = l1 * al1 + ls1; m1 = mn1;
#pragma unroll
        for (int nf = 0; nf < 8; nf++) {
            o[nf][0] *= al0; o[nf][1] *= al0;
            o[nf][2] *= al1; o[nf][3] *= al1;
        }
        __syncwarp();

        // --- O += P @ V (warp tile 16 x 64) ---
#pragma unroll
        for (int ks = 0; ks < 8; ks++) {
            uint a0 = Ps[g * AP + ks * 8 + c];
            uint a1 = Ps[(g + 8) * AP + ks * 8 + c];
            uint a2 = Ps[g * AP + ks * 8 + c + 4];
            uint a3 = Ps[(g + 8) * AP + ks * 8 + c + 4];
#pragma unroll
            for (int nf = 0; nf < 8; nf++) {
                uint b0 = Vs[(ks * 8 + c) * AP + nf * 8 + g];
                uint b1 = Vs[(ks * 8 + c + 4) * AP + nf * 8 + g];
                mma_tf32(o[nf][0], o[nf][1], o[nf][2], o[nf][3],
                         a0, a1, a2, a3, b0, b1);
            }
        }
    }

    // Epilogue: write ctx as tf32 bits, layout [B,L,H*DH]
    float inv0 = 1.0f / l0, inv1 = 1.0f / l1;
    int r0 = q0 + w * 16 + g;
    int r1 = r0 + 8;
#pragma unroll
    for (int nf = 0; nf < 8; nf++) {
        int col = h * 64 + nf * 8 + 2 * c;
        uint2 u0, u1;
        u0.x = f2tf(o[nf][0] * inv0); u0.y = f2tf(o[nf][1] * inv0);
        u1.x = f2tf(o[nf][2] * inv1); u1.y = f2tf(o[nf][3] * inv1);
        *(uint2*)(g_ctx + ((size_t)(bb * L_ + r0)) * 1024 + col) = u0;
        *(uint2*)(g_ctx + ((size_t)(bb * L_ + r1)) * 1024 + col) = u1;
    }
}

// ---------------------------------------------------------------------------
// GEMM 2: y = x + ctx @ W_out^T + b_out  (M=4096, N=1024, K=1024), tf32 MMA
// ctx already tf32 bits; W converted on load. Output fp32 to g_y.
// ---------------------------------------------------------------------------
__global__ __launch_bounds__(256) void out_gemm_tf32(
    const float* __restrict__ X,     // residual x [4096,1024]
    const float* __restrict__ W,     // out_proj_w [1024,1024]
    const float* __restrict__ bias)  // [1024]
{
    __shared__ uint As[32][132];
    __shared__ uint Bs[32][132];
    const int bn = blockIdx.x, bm = blockIdx.y;
    const int tid = threadIdx.x;
    const int lane = tid & 31, wid = tid >> 5;
    const int wm = (wid & 1) * 64, wn = (wid >> 1) * 32;
    const int g = lane >> 2, c = lane & 3;

    float acc[4][4][4];
#pragma unroll
    for (int mf = 0; mf < 4; mf++)
#pragma unroll
        for (int nf = 0; nf < 4; nf++)
#pragma unroll
            for (int r = 0; r < 4; r++) acc[mf][nf][r] = 0.f;

    const uint*  Ab = g_ctx + (size_t)(bm * 128) * 1024;
    const float* Wb = W + (size_t)(bn * 128) * 1024;

    for (int k0 = 0; k0 < 1024; k0 += 32) {
        __syncthreads();
#pragma unroll
        for (int i = 0; i < 4; i++) {
            int f = tid + i * 256;
            int m = f >> 3, kq = f & 7;
            uint4 va = *(const uint4*)(Ab + (size_t)m * 1024 + k0 + kq * 4);
            As[kq * 4 + 0][m] = va.x;
            As[kq * 4 + 1][m] = va.y;
            As[kq * 4 + 2][m] = va.z;
            As[kq * 4 + 3][m] = va.w;
            float4 vb = *(const float4*)(Wb + (size_t)m * 1024 + k0 + kq * 4);
            Bs[kq * 4 + 0][m] = f2tf(vb.x);
            Bs[kq * 4 + 1][m] = f2tf(vb.y);
            Bs[kq * 4 + 2][m] = f2tf(vb.z);
            Bs[kq * 4 + 3][m] = f2tf(vb.w);
        }
        __syncthreads();
#pragma unroll
        for (int ks = 0; ks < 4; ks++) {
            uint a[4][4], b[4][2];
#pragma unroll
            for (int mf = 0; mf < 4; mf++) {
                a[mf][0] = As[ks * 8 + c][wm + mf * 16 + g];
                a[mf][1] = As[ks * 8 + c][wm + mf * 16 + g + 8];
                a[mf][2] = As[ks * 8 + c + 4][wm + mf * 16 + g];
                a[mf][3] = As[ks * 8 + c + 4][wm + mf * 16 + g + 8];
            }
#pragma unroll
            for (int nf = 0; nf < 4; nf++) {
                b[nf][0] = Bs[ks * 8 + c][wn + nf * 8 + g];
                b[nf][1] = Bs[ks * 8 + c + 4][wn + nf * 8 + g];
            }
#pragma unroll
            for (int mf = 0; mf < 4; mf++)
#pragma unroll
                for (int nf = 0; nf < 4; nf++)
                    mma_tf32(acc[mf][nf][0], acc[mf][nf][1], acc[mf][nf][2], acc[mf][nf][3],
                             a[mf][0], a[mf][1], a[mf][2], a[mf][3],
                             b[nf][0], b[nf][1]);
        }
    }

#pragma unroll
    for (int mf = 0; mf < 4; mf++) {
#pragma unroll
        for (int rr = 0; rr < 2; rr++) {
            int ri = bm * 128 + wm + mf * 16 + g + rr * 8;
#pragma unroll
            for (int nf = 0; nf < 4; nf++) {
                int n = bn * 128 + wn + nf * 8 + 2 * c;
                float2 v;
                v.x = acc[mf][nf][rr * 2 + 0] + bias[n]     + X[(size_t)ri * 1024 + n];
                v.y = acc[mf][nf][rr * 2 + 1] + bias[n + 1] + X[(size_t)ri * 1024 + n + 1];
                *(float2*)(g_y + (size_t)ri * 1024 + n) = v;
            }
        }
    }
}

// ---------------------------------------------------------------------------
// LayerNorm over last dim (1024), one block per token row
// ---------------------------------------------------------------------------
__global__ __launch_bounds__(256) void ln_kernel(
    const float* __restrict__ gamma,
    const float* __restrict__ beta,
    float* __restrict__ out)
{
    const int row = blockIdx.x;
    const float* yr = g_y + (size_t)row * 1024;
    const int tid = threadIdx.x;

    float s = 0.f, sq = 0.f;
#pragma unroll
    for (int i = tid; i < 1024; i += 256) {
        float v = yr[i];
        s += v;
        sq += v * v;
    }
#pragma unroll
    for (int off = 16; off > 0; off >>= 1) {
        s  += __shfl_xor_sync(0xffffffffu, s, off);
        sq += __shfl_xor_sync(0xffffffffu, sq, off);
    }
    __shared__ float ws[8], wq[8];
    __shared__ float mu_s, rstd_s;
    int w = tid >> 5;
    if ((tid & 31) == 0) { ws[w] = s; wq[w] = sq; }
    __syncthreads();
    if (tid == 0) {
        float S = 0.f, Q = 0.f;
#pragma unroll
        for (int i = 0; i < 8; i++) { S += ws[i]; Q += wq[i]; }
        float mu = S * (1.0f / 1024.0f);
        float var = Q * (1.0f / 1024.0f) - mu * mu;
        mu_s = mu;
        rstd_s = rsqrtf(var + 1e-5f);
    }
    __syncthreads();
    float mu = mu_s, rstd = rstd_s;
#pragma unroll
    for (int i = tid; i < 1024; i += 256) {
        out[(size_t)row * 1024 + i] = (yr[i] - mu) * rstd * gamma[i] + beta[i];
    }
}

// ---------------------------------------------------------------------------
extern "C" void kernel_launch(void* const* d_in, const int* in_sizes, int n_in,
                              void* d_out, int out_size)
{
    const float* x      = (const float*)d_in[0];
    // d_in[1] = market_info: softmax-invariant constant, unused
    const float* w_in   = (const float*)d_in[2];
    const float* b_in   = (const float*)d_in[3];
    const float* w_out  = (const float*)d_in[4];
    const float* b_out  = (const float*)d_in[5];
    const float* gamma  = (const float*)d_in[6];
    const float* beta   = (const float*)d_in[7];
    float* out = (float*)d_out;

    // QKV projection (tf32 tensor cores)
    qkv_gemm_tf32<<<dim3(24, 32), 256>>>(x, w_in, b_in);

    // Attention: smem = (3*64 + 4*16) * 68 uints = 69632 B
    const int attn_smem = (3 * 64 * AP + 4 * 16 * AP) * (int)sizeof(uint);
    cudaFuncSetAttribute(attn_tf32, cudaFuncAttributeMaxDynamicSharedMemorySize,
                         attn_smem);
    attn_tf32<<<dim3(L_ / 64, B_ * H_), 128, attn_smem>>>();

    // Output projection + residual
    out_gemm_tf32<<<dim3(8, 32), 256>>>(x, w_out, b_out);

    // LayerNorm
    ln_kernel<<<NT, 256>>>(gamma, beta, out);
}

// round 8
// speedup vs baseline: 2.7750x; 1.2686x over previous
#include <cuda_runtime.h>
#include <math.h>

// Problem constants
#define B_  2
#define L_  2048
#define D_  1024
#define H_  16
#define DH_ 64
#define NT  (B_*L_)          // 4096 tokens
#define ND  (B_*H_*L_*DH_)   // 4M elements per Q/K/V

typedef unsigned int uint;

// Scratch (device-global statics), all raw fp32 (mma.sync tf32 truncates in HW)
__device__ float g_q[ND];
__device__ float g_k[ND];
__device__ float g_v[ND];
__device__ float g_ctx[NT * D_];
__device__ float g_y[NT * D_];

// ---------------------------------------------------------------------------
// helpers
// ---------------------------------------------------------------------------
__device__ __forceinline__ void mma_tf32(
    float& c0, float& c1, float& c2, float& c3,
    uint a0, uint a1, uint a2, uint a3, uint b0, uint b1)
{
    asm volatile(
        "mma.sync.aligned.m16n8k8.row.col.f32.tf32.tf32.f32 "
        "{%0,%1,%2,%3}, {%4,%5,%6,%7}, {%8,%9}, {%0,%1,%2,%3};"
        : "+f"(c0), "+f"(c1), "+f"(c2), "+f"(c3)
        : "r"(a0), "r"(a1), "r"(a2), "r"(a3), "r"(b0), "r"(b1));
}

__device__ __forceinline__ uint smem_u32(const void* p) {
    uint a;
    asm("{ .reg .u64 t; cvta.to.shared.u64 t, %1; cvt.u32.u64 %0, t; }"
        : "=r"(a) : "l"(p));
    return a;
}

__device__ __forceinline__ void cpa16(void* sdst, const void* gsrc) {
    uint d = smem_u32(sdst);
    asm volatile("cp.async.cg.shared.global [%0], [%1], 16;"
                 :: "r"(d), "l"(gsrc) : "memory");
}
#define CPA_COMMIT() asm volatile("cp.async.commit_group;" ::: "memory")
#define CPA_WAIT1()  asm volatile("cp.async.wait_group 1;" ::: "memory")
#define CPA_WAIT0()  asm volatile("cp.async.wait_group 0;" ::: "memory")

// ---------------------------------------------------------------------------
// GEMM mainloop (shared): acc[128x128] += A[bm*128.., K=1024] @ W[bn*128..]^T
// cp.async double-buffered, k-stage 32, [m][k] smem layout pitch 36 (bank-
// conflict-free fragment loads: bank = 4g + c, distinct over the warp).
// 256 threads, 8 warps (2m x 4n), warp tile 64x32.
// ---------------------------------------------------------------------------
#define GP 36   // gemm smem pitch (floats)

__device__ __forceinline__ void gemm_copy_stage(
    uint* As, uint* Bs, const float* Ab, const float* Wb, int k0)
{
    const int tid = threadIdx.x;
#pragma unroll
    for (int i = 0; i < 4; i++) {
        int cidx = tid + i * 256;           // 0..1023
        int row = cidx >> 3, kc = cidx & 7; // 8 x 16B chunks per 32-float row
        cpa16(As + row * GP + kc * 4, Ab + (size_t)row * 1024 + k0 + kc * 4);
        cpa16(Bs + row * GP + kc * 4, Wb + (size_t)row * 1024 + k0 + kc * 4);
    }
}

__device__ __forceinline__ void gemm_mainloop(
    uint* sA, uint* sB, const float* Ab, const float* Wb, float acc[4][4][4])
{
    const int tid = threadIdx.x;
    const int lane = tid & 31, wid = tid >> 5;
    const int wm = (wid & 1) * 64, wn = (wid >> 1) * 32;
    const int g = lane >> 2, c = lane & 3;

#pragma unroll
    for (int mf = 0; mf < 4; mf++)
#pragma unroll
        for (int nf = 0; nf < 4; nf++)
#pragma unroll
            for (int r = 0; r < 4; r++) acc[mf][nf][r] = 0.f;

    gemm_copy_stage(sA, sB, Ab, Wb, 0);
    CPA_COMMIT();

    for (int it = 0; it < 32; it++) {
        const int s = it & 1;
        if (it + 1 < 32) {
            gemm_copy_stage(sA + ((it + 1) & 1) * (128 * GP),
                            sB + ((it + 1) & 1) * (128 * GP),
                            Ab, Wb, (it + 1) * 32);
            CPA_COMMIT();
            CPA_WAIT1();
        } else {
            CPA_WAIT0();
        }
        __syncthreads();
        const uint* A = sA + s * (128 * GP);
        const uint* Bt = sB + s * (128 * GP);
#pragma unroll
        for (int ks = 0; ks < 4; ks++) {
            uint a[4][4], b[4][2];
#pragma unroll
            for (int mf = 0; mf < 4; mf++) {
                const uint* p = A + (wm + mf * 16 + g) * GP + ks * 8 + c;
                a[mf][0] = p[0];
                a[mf][1] = p[8 * GP];
                a[mf][2] = p[4];
                a[mf][3] = p[8 * GP + 4];
            }
#pragma unroll
            for (int nf = 0; nf < 4; nf++) {
                const uint* p = Bt + (wn + nf * 8 + g) * GP + ks * 8 + c;
                b[nf][0] = p[0];
                b[nf][1] = p[4];
            }
#pragma unroll
            for (int mf = 0; mf < 4; mf++)
#pragma unroll
                for (int nf = 0; nf < 4; nf++)
                    mma_tf32(acc[mf][nf][0], acc[mf][nf][1], acc[mf][nf][2], acc[mf][nf][3],
                             a[mf][0], a[mf][1], a[mf][2], a[mf][3],
                             b[nf][0], b[nf][1]);
        }
        __syncthreads();
    }
}

// ---------------------------------------------------------------------------
// GEMM 1: qkv = x @ W_in^T + b_in, scatter into Q/K/V [B,H,L,DH]
// grid (24, 32), 256 threads
// ---------------------------------------------------------------------------
__global__ __launch_bounds__(256) void qkv_gemm(
    const float* __restrict__ A,
    const float* __restrict__ W,
    const float* __restrict__ bias)
{
    extern __shared__ uint smem[];
    uint* sA = smem;
    uint* sB = smem + 2 * 128 * GP;
    const int bn = blockIdx.x, bm = blockIdx.y;

    float acc[4][4][4];
    gemm_mainloop(sA, sB, A + (size_t)bm * 128 * 1024,
                  W + (size_t)bn * 128 * 1024, acc);

    const int tid = threadIdx.x;
    const int lane = tid & 31, wid = tid >> 5;
    const int wm = (wid & 1) * 64, wn = (wid >> 1) * 32;
    const int g = lane >> 2, c = lane & 3;

#pragma unroll
    for (int mf = 0; mf < 4; mf++) {
#pragma unroll
        for (int rr = 0; rr < 2; rr++) {
            int ri = bm * 128 + wm + mf * 16 + g + rr * 8;
            int bb = ri >> 11, l = ri & 2047;
#pragma unroll
            for (int nf = 0; nf < 4; nf++) {
                int n = bn * 128 + wn + nf * 8 + 2 * c;
                float2 v;
                v.x = acc[mf][nf][rr * 2 + 0] + bias[n];
                v.y = acc[mf][nf][rr * 2 + 1] + bias[n + 1];
                int part = n >> 10;          // uniform per CTA
                int hd = n & 1023;
                int h = hd >> 6, dh = hd & 63;
                size_t dst = ((size_t)(bb * H_ + h) * L_ + l) * DH_ + dh;
                float* base = (part == 0) ? g_q : (part == 1) ? g_k : g_v;
                *(float2*)(base + dst) = v;
            }
        }
    }
}

// ---------------------------------------------------------------------------
// GEMM 2: y = x + ctx @ W_out^T + b_out ; grid (8, 32), 256 threads
// ---------------------------------------------------------------------------
__global__ __launch_bounds__(256) void out_gemm(
    const float* __restrict__ X,
    const float* __restrict__ W,
    const float* __restrict__ bias)
{
    extern __shared__ uint smem[];
    uint* sA = smem;
    uint* sB = smem + 2 * 128 * GP;
    const int bn = blockIdx.x, bm = blockIdx.y;

    float acc[4][4][4];
    gemm_mainloop(sA, sB, g_ctx + (size_t)bm * 128 * 1024,
                  W + (size_t)bn * 128 * 1024, acc);

    const int tid = threadIdx.x;
    const int lane = tid & 31, wid = tid >> 5;
    const int wm = (wid & 1) * 64, wn = (wid >> 1) * 32;
    const int g = lane >> 2, c = lane & 3;

#pragma unroll
    for (int mf = 0; mf < 4; mf++) {
#pragma unroll
        for (int rr = 0; rr < 2; rr++) {
            int ri = bm * 128 + wm + mf * 16 + g + rr * 8;
#pragma unroll
            for (int nf = 0; nf < 4; nf++) {
                int n = bn * 128 + wn + nf * 8 + 2 * c;
                float2 v;
                v.x = acc[mf][nf][rr * 2 + 0] + bias[n]     + X[(size_t)ri * 1024 + n];
                v.y = acc[mf][nf][rr * 2 + 1] + bias[n + 1] + X[(size_t)ri * 1024 + n + 1];
                *(float2*)(g_y + (size_t)ri * 1024 + n) = v;
            }
        }
    }
}

// ---------------------------------------------------------------------------
// Flash attention, tf32 mma.sync. Block = one (b,h) x 128 q-rows, 8 warps
// (16 rows each), K/V streamed in 64-key tiles, cp.async double-buffered.
// Softmax is invariant to the per-batch "vol" constant -> market_info dropped.
// ---------------------------------------------------------------------------
#define AP 68   // attn smem pitch (floats)
__global__ __launch_bounds__(256) void attn_tf32()
{
    extern __shared__ float sm[];
    float* Qs  = sm;                      // 128 x AP
    float* Ks  = Qs + 128 * AP;           // 2 x 64 x AP
    float* Vs  = Ks + 2 * 64 * AP;        // 2 x 64 x AP
    float* Psw = Vs + 2 * 64 * AP;        // 8 warps x 16 x AP

    const int bh = blockIdx.y;            // 0..31
    const int bb = bh >> 4, h = bh & 15;
    const int q0 = blockIdx.x * 128;
    const int tid = threadIdx.x;
    const int lane = tid & 31, w = tid >> 5;
    const int g = lane >> 2, c = lane & 3;
    float* Ps = Psw + w * 16 * AP;
    const uint* Psu = (const uint*)Ps;
    const uint* Qsu = (const uint*)Qs;

    const float* Qg = g_q + ((size_t)bh * L_ + q0) * DH_;
    const float* Kg = g_k + (size_t)bh * L_ * DH_;
    const float* Vg = g_v + (size_t)bh * L_ * DH_;

    // Load Q tile (128 x 64)
#pragma unroll
    for (int i = 0; i < 8; i++) {
        int f = tid + i * 256;            // 0..2047 float4s
        int r = f >> 4, c4 = f & 15;
        *(float4*)(Qs + r * AP + c4 * 4) =
            *(const float4*)(Qg + (size_t)r * 64 + c4 * 4);
    }

    // Prefetch K/V tile 0
#pragma unroll
    for (int i = 0; i < 4; i++) {
        int cidx = tid + i * 256;         // 0..1023
        int r = cidx >> 4, kc = cidx & 15;
        cpa16(Ks + r * AP + kc * 4, Kg + (size_t)r * 64 + kc * 4);
        cpa16(Vs + r * AP + kc * 4, Vg + (size_t)r * 64 + kc * 4);
    }
    CPA_COMMIT();

    float m0 = -1e30f, m1 = -1e30f, l0 = 0.f, l1 = 0.f;
    float o[8][4];
#pragma unroll
    for (int nf = 0; nf < 8; nf++)
#pragma unroll
        for (int r = 0; r < 4; r++) o[nf][r] = 0.f;

    for (int kt = 0; kt < L_ / 64; kt++) {
        const int s = kt & 1;
        if (kt + 1 < L_ / 64) {
            const float* Kt = Kg + (size_t)(kt + 1) * 64 * 64;
            const float* Vt = Vg + (size_t)(kt + 1) * 64 * 64;
            float* Kd = Ks + ((kt + 1) & 1) * 64 * AP;
            float* Vd = Vs + ((kt + 1) & 1) * 64 * AP;
#pragma unroll
            for (int i = 0; i < 4; i++) {
                int cidx = tid + i * 256;
                int r = cidx >> 4, kc = cidx & 15;
                cpa16(Kd + r * AP + kc * 4, Kt + (size_t)r * 64 + kc * 4);
                cpa16(Vd + r * AP + kc * 4, Vt + (size_t)r * 64 + kc * 4);
            }
            CPA_COMMIT();
            CPA_WAIT1();
        } else {
            CPA_WAIT0();
        }
        __syncthreads();
        const uint* Ku = (const uint*)(Ks + s * 64 * AP);
        const uint* Vu = (const uint*)(Vs + s * 64 * AP);

        // --- S = Q @ K^T (warp tile 16 x 64) ---
        float sc[8][4];
#pragma unroll
        for (int nf = 0; nf < 8; nf++)
#pragma unroll
            for (int r = 0; r < 4; r++) sc[nf][r] = 0.f;
#pragma unroll
        for (int ks = 0; ks < 8; ks++) {
            uint a0 = Qsu[(w * 16 + g) * AP + ks * 8 + c];
            uint a1 = Qsu[(w * 16 + g + 8) * AP + ks * 8 + c];
            uint a2 = Qsu[(w * 16 + g) * AP + ks * 8 + c + 4];
            uint a3 = Qsu[(w * 16 + g + 8) * AP + ks * 8 + c + 4];
#pragma unroll
            for (int nf = 0; nf < 8; nf++) {
                uint b0 = Ku[(nf * 8 + g) * AP + ks * 8 + c];
                uint b1 = Ku[(nf * 8 + g) * AP + ks * 8 + c + 4];
                mma_tf32(sc[nf][0], sc[nf][1], sc[nf][2], sc[nf][3],
                         a0, a1, a2, a3, b0, b1);
            }
        }

        // --- online softmax (rows g and g+8 of this warp's 16) ---
        float mx0 = -1e30f, mx1 = -1e30f;
#pragma unroll
        for (int nf = 0; nf < 8; nf++) {
#pragma unroll
            for (int r = 0; r < 4; r++) sc[nf][r] *= 0.125f;
            mx0 = fmaxf(mx0, fmaxf(sc[nf][0], sc[nf][1]));
            mx1 = fmaxf(mx1, fmaxf(sc[nf][2], sc[nf][3]));
        }
        mx0 = fmaxf(mx0, __shfl_xor_sync(0xffffffffu, mx0, 1));
        mx0 = fmaxf(mx0, __shfl_xor_sync(0xffffffffu, mx0, 2));
        mx1 = fmaxf(mx1, __shfl_xor_sync(0xffffffffu, mx1, 1));
        mx1 = fmaxf(mx1, __shfl_xor_sync(0xffffffffu, mx1, 2));
        float mn0 = fmaxf(m0, mx0), mn1 = fmaxf(m1, mx1);
        float al0 = __expf(m0 - mn0), al1 = __expf(m1 - mn1);
        float ls0 = 0.f, ls1 = 0.f;
#pragma unroll
        for (int nf = 0; nf < 8; nf++) {
            float p0 = __expf(sc[nf][0] - mn0);
            float p1 = __expf(sc[nf][1] - mn0);
            float p2 = __expf(sc[nf][2] - mn1);
            float p3 = __expf(sc[nf][3] - mn1);
            ls0 += p0 + p1;
            ls1 += p2 + p3;
            Ps[g * AP + nf * 8 + 2 * c]           = p0;
            Ps[g * AP + nf * 8 + 2 * c + 1]       = p1;
            Ps[(g + 8) * AP + nf * 8 + 2 * c]     = p2;
            Ps[(g + 8) * AP + nf * 8 + 2 * c + 1] = p3;
        }
        ls0 += __shfl_xor_sync(0xffffffffu, ls0, 1);
        ls0 += __shfl_xor_sync(0xffffffffu, ls0, 2);
        ls1 += __shfl_xor_sync(0xffffffffu, ls1, 1);
        ls1 += __shfl_xor_sync(0xffffffffu, ls1, 2);
        l0 = l0 * al0 + ls0; m0 = mn0;
        l1 = l1 * al1 + ls1; m1 = mn1;
#pragma unroll
        for (int nf = 0; nf < 8; nf++) {
            o[nf][0] *= al0; o[nf][1] *= al0;
            o[nf][2] *= al1; o[nf][3] *= al1;
        }
        __syncwarp();

        // --- O += P @ V (warp tile 16 x 64) ---
#pragma unroll
        for (int ks = 0; ks < 8; ks++) {
            uint a0 = Psu[g * AP + ks * 8 + c];
            uint a1 = Psu[(g + 8) * AP + ks * 8 + c];
            uint a2 = Psu[g * AP + ks * 8 + c + 4];
            uint a3 = Psu[(g + 8) * AP + ks * 8 + c + 4];
#pragma unroll
            for (int nf = 0; nf < 8; nf++) {
                uint b0 = Vu[(ks * 8 + c) * AP + nf * 8 + g];
                uint b1 = Vu[(ks * 8 + c + 4) * AP + nf * 8 + g];
                mma_tf32(o[nf][0], o[nf][1], o[nf][2], o[nf][3],
                         a0, a1, a2, a3, b0, b1);
            }
        }
        __syncthreads();   // all warps done with this K/V buffer
    }

    // Epilogue: write ctx, layout [B,L,H*DH]
    float inv0 = 1.0f / l0, inv1 = 1.0f / l1;
    int r0 = q0 + w * 16 + g;
    int r1 = r0 + 8;
#pragma unroll
    for (int nf = 0; nf < 8; nf++) {
        int col = h * 64 + nf * 8 + 2 * c;
        float2 u0, u1;
        u0.x = o[nf][0] * inv0; u0.y = o[nf][1] * inv0;
        u1.x = o[nf][2] * inv1; u1.y = o[nf][3] * inv1;
        *(float2*)(g_ctx + ((size_t)(bb * L_ + r0)) * 1024 + col) = u0;
        *(float2*)(g_ctx + ((size_t)(bb * L_ + r1)) * 1024 + col) = u1;
    }
}

// ---------------------------------------------------------------------------
// LayerNorm over last dim (1024), one block per token row
// ---------------------------------------------------------------------------
__global__ __launch_bounds__(256) void ln_kernel(
    const float* __restrict__ gamma,
    const float* __restrict__ beta,
    float* __restrict__ out)
{
    const int row = blockIdx.x;
    const float* yr = g_y + (size_t)row * 1024;
    const int tid = threadIdx.x;

    float s = 0.f, sq = 0.f;
#pragma unroll
    for (int i = tid; i < 1024; i += 256) {
        float v = yr[i];
        s += v;
        sq += v * v;
    }
#pragma unroll
    for (int off = 16; off > 0; off >>= 1) {
        s  += __shfl_xor_sync(0xffffffffu, s, off);
        sq += __shfl_xor_sync(0xffffffffu, sq, off);
    }
    __shared__ float ws[8], wq[8];
    __shared__ float mu_s, rstd_s;
    int w = tid >> 5;
    if ((tid & 31) == 0) { ws[w] = s; wq[w] = sq; }
    __syncthreads();
    if (tid == 0) {
        float S = 0.f, Q = 0.f;
#pragma unroll
        for (int i = 0; i < 8; i++) { S += ws[i]; Q += wq[i]; }
        float mu = S * (1.0f / 1024.0f);
        float var = Q * (1.0f / 1024.0f) - mu * mu;
        mu_s = mu;
        rstd_s = rsqrtf(var + 1e-5f);
    }
    __syncthreads();
    float mu = mu_s, rstd = rstd_s;
#pragma unroll
    for (int i = tid; i < 1024; i += 256) {
        out[(size_t)row * 1024 + i] = (yr[i] - mu) * rstd * gamma[i] + beta[i];
    }
}

// ---------------------------------------------------------------------------
extern "C" void kernel_launch(void* const* d_in, const int* in_sizes, int n_in,
                              void* d_out, int out_size)
{
    const float* x      = (const float*)d_in[0];
    // d_in[1] = market_info: softmax-invariant constant, unused
    const float* w_in   = (const float*)d_in[2];
    const float* b_in   = (const float*)d_in[3];
    const float* w_out  = (const float*)d_in[4];
    const float* b_out  = (const float*)d_in[5];
    const float* gamma  = (const float*)d_in[6];
    const float* beta   = (const float*)d_in[7];
    float* out = (float*)d_out;

    // GEMM smem: 2 buffers x (A + B) x 128 x 36 floats = 73728 B
    const int gemm_smem = 4 * 128 * GP * (int)sizeof(float);
    cudaFuncSetAttribute(qkv_gemm, cudaFuncAttributeMaxDynamicSharedMemorySize, gemm_smem);
    cudaFuncSetAttribute(out_gemm, cudaFuncAttributeMaxDynamicSharedMemorySize, gemm_smem);

    // QKV projection
    qkv_gemm<<<dim3(24, 32), 256, gemm_smem>>>(x, w_in, b_in);

    // Attention: smem = (128 + 4*64 + 8*16) * AP floats = 512*68*4 = 139264 B
    const int attn_smem = 512 * AP * (int)sizeof(float);
    cudaFuncSetAttribute(attn_tf32, cudaFuncAttributeMaxDynamicSharedMemorySize,
                         attn_smem);
    attn_tf32<<<dim3(L_ / 128, B_ * H_), 256, attn_smem>>>();

    // Output projection + residual
    out_gemm<<<dim3(8, 32), 256, gemm_smem>>>(x, w_out, b_out);

    // LayerNorm
    ln_kernel<<<NT, 256>>>(gamma, beta, out);
}

// round 9
// speedup vs baseline: 3.7928x; 1.3668x over previous
#include <cuda_runtime.h>
#include <math.h>

// Problem constants
#define B_  2
#define L_  2048
#define D_  1024
#define H_  16
#define DH_ 64
#define NT  (B_*L_)          // 4096 tokens
#define ND  (B_*H_*L_*DH_)   // 4M elements per Q/K/V

typedef unsigned int uint;

// Scratch. g_v is stored TRANSPOSED: [B,H,DH,L]
__device__ float g_q[ND];
__device__ float g_k[ND];
__device__ float g_v[ND];
__device__ float g_ctx[NT * D_];
__device__ float g_y[NT * D_];

// ---------------------------------------------------------------------------
// helpers
// ---------------------------------------------------------------------------
__device__ __forceinline__ void mma_tf32(
    float& c0, float& c1, float& c2, float& c3,
    uint a0, uint a1, uint a2, uint a3, uint b0, uint b1)
{
    asm volatile(
        "mma.sync.aligned.m16n8k8.row.col.f32.tf32.tf32.f32 "
        "{%0,%1,%2,%3}, {%4,%5,%6,%7}, {%8,%9}, {%0,%1,%2,%3};"
        : "+f"(c0), "+f"(c1), "+f"(c2), "+f"(c3)
        : "r"(a0), "r"(a1), "r"(a2), "r"(a3), "r"(b0), "r"(b1));
}

__device__ __forceinline__ uint smem_u32(const void* p) {
    uint a;
    asm("{ .reg .u64 t; cvta.to.shared.u64 t, %1; cvt.u32.u64 %0, t; }"
        : "=r"(a) : "l"(p));
    return a;
}

__device__ __forceinline__ void cpa16(void* sdst, const void* gsrc) {
    uint d = smem_u32(sdst);
    asm volatile("cp.async.cg.shared.global [%0], [%1], 16;"
                 :: "r"(d), "l"(gsrc) : "memory");
}
#define CPA_COMMIT() asm volatile("cp.async.commit_group;" ::: "memory")
#define CPA_WAIT1()  asm volatile("cp.async.wait_group 1;" ::: "memory")
#define CPA_WAIT0()  asm volatile("cp.async.wait_group 0;" ::: "memory")

// ---------------------------------------------------------------------------
// GEMM mainloop: acc[128x128] += A[bm*128.., K=1024] @ W[bn*128..]^T
// cp.async double-buffered, k-stage 32, [m][k] smem, pitch 40 (8g+2c banks,
// conflict-free LDS.64 fragment pairs under the permuted-k convention
// sigma(c)=2c, sigma(c+4)=2c+1 applied identically to A and B).
// 256 threads, 8 warps (2m x 4n), warp tile 64x32.
// ---------------------------------------------------------------------------
#define GP 40   // gemm smem pitch (floats)

__device__ __forceinline__ void gemm_copy_stage(
    float* As, float* Bs, const float* Ab, const float* Wb, int k0)
{
    const int tid = threadIdx.x;
#pragma unroll
    for (int i = 0; i < 4; i++) {
        int cidx = tid + i * 256;           // 0..1023
        int row = cidx >> 3, kc = cidx & 7; // 8 x 16B chunks per 32-float row
        cpa16(As + row * GP + kc * 4, Ab + (size_t)row * 1024 + k0 + kc * 4);
        cpa16(Bs + row * GP + kc * 4, Wb + (size_t)row * 1024 + k0 + kc * 4);
    }
}

__device__ __forceinline__ void gemm_mainloop(
    float* sA, float* sB, const float* Ab, const float* Wb, float acc[4][4][4])
{
    const int tid = threadIdx.x;
    const int lane = tid & 31, wid = tid >> 5;
    const int wm = (wid & 1) * 64, wn = (wid >> 1) * 32;
    const int g = lane >> 2, c = lane & 3;

#pragma unroll
    for (int mf = 0; mf < 4; mf++)
#pragma unroll
        for (int nf = 0; nf < 4; nf++)
#pragma unroll
            for (int r = 0; r < 4; r++) acc[mf][nf][r] = 0.f;

    gemm_copy_stage(sA, sB, Ab, Wb, 0);
    CPA_COMMIT();

    for (int it = 0; it < 32; it++) {
        const int s = it & 1;
        if (it + 1 < 32) {
            gemm_copy_stage(sA + ((it + 1) & 1) * (128 * GP),
                            sB + ((it + 1) & 1) * (128 * GP),
                            Ab, Wb, (it + 1) * 32);
            CPA_COMMIT();
            CPA_WAIT1();
        } else {
            CPA_WAIT0();
        }
        __syncthreads();
        const float* A  = sA + s * (128 * GP);
        const float* Bt = sB + s * (128 * GP);
#pragma unroll
        for (int ks = 0; ks < 4; ks++) {
            uint a[4][4], b[4][2];
#pragma unroll
            for (int mf = 0; mf < 4; mf++) {
                float2 f0 = *(const float2*)(A + (wm + mf * 16 + g) * GP + ks * 8 + 2 * c);
                float2 f1 = *(const float2*)(A + (wm + mf * 16 + g + 8) * GP + ks * 8 + 2 * c);
                a[mf][0] = __float_as_uint(f0.x);
                a[mf][1] = __float_as_uint(f1.x);
                a[mf][2] = __float_as_uint(f0.y);
                a[mf][3] = __float_as_uint(f1.y);
            }
#pragma unroll
            for (int nf = 0; nf < 4; nf++) {
                float2 fb = *(const float2*)(Bt + (wn + nf * 8 + g) * GP + ks * 8 + 2 * c);
                b[nf][0] = __float_as_uint(fb.x);
                b[nf][1] = __float_as_uint(fb.y);
            }
#pragma unroll
            for (int mf = 0; mf < 4; mf++)
#pragma unroll
                for (int nf = 0; nf < 4; nf++)
                    mma_tf32(acc[mf][nf][0], acc[mf][nf][1], acc[mf][nf][2], acc[mf][nf][3],
                             a[mf][0], a[mf][1], a[mf][2], a[mf][3],
                             b[nf][0], b[nf][1]);
        }
        __syncthreads();
    }
}

// ---------------------------------------------------------------------------
// GEMM 1: qkv = x @ W_in^T + b_in, scatter into Q/K [B,H,L,DH], V [B,H,DH,L]
// grid (24, 32), 256 threads
// ---------------------------------------------------------------------------
__global__ __launch_bounds__(256) void qkv_gemm(
    const float* __restrict__ A,
    const float* __restrict__ W,
    const float* __restrict__ bias)
{
    extern __shared__ float smem[];
    float* sA = smem;
    float* sB = smem + 2 * 128 * GP;
    const int bn = blockIdx.x, bm = blockIdx.y;

    float acc[4][4][4];
    gemm_mainloop(sA, sB, A + (size_t)bm * 128 * 1024,
                  W + (size_t)bn * 128 * 1024, acc);

    const int tid = threadIdx.x;
    const int lane = tid & 31, wid = tid >> 5;
    const int wm = (wid & 1) * 64, wn = (wid >> 1) * 32;
    const int g = lane >> 2, c = lane & 3;
    const int part = (bn * 128) >> 10;       // uniform per CTA: 0=Q 1=K 2=V

#pragma unroll
    for (int mf = 0; mf < 4; mf++) {
#pragma unroll
        for (int rr = 0; rr < 2; rr++) {
            int ri = bm * 128 + wm + mf * 16 + g + rr * 8;
            int bb = ri >> 11, l = ri & 2047;
#pragma unroll
            for (int nf = 0; nf < 4; nf++) {
                int n = bn * 128 + wn + nf * 8 + 2 * c;
                float2 v;
                v.x = acc[mf][nf][rr * 2 + 0] + bias[n];
                v.y = acc[mf][nf][rr * 2 + 1] + bias[n + 1];
                int hd = n & 1023;
                int h = hd >> 6, dh = hd & 63;
                if (part == 2) {
                    // V transposed: [B,H,DH,L]
                    size_t base = ((size_t)(bb * H_ + h) * DH_ + dh) * L_ + l;
                    g_v[base]      = v.x;
                    g_v[base + L_] = v.y;
                } else {
                    size_t dst = ((size_t)(bb * H_ + h) * L_ + l) * DH_ + dh;
                    float* basep = (part == 0) ? g_q : g_k;
                    *(float2*)(basep + dst) = v;
                }
            }
        }
    }
}

// ---------------------------------------------------------------------------
// GEMM 2: y = x + ctx @ W_out^T + b_out ; grid (8, 32), 256 threads
// ---------------------------------------------------------------------------
__global__ __launch_bounds__(256) void out_gemm(
    const float* __restrict__ X,
    const float* __restrict__ W,
    const float* __restrict__ bias)
{
    extern __shared__ float smem[];
    float* sA = smem;
    float* sB = smem + 2 * 128 * GP;
    const int bn = blockIdx.x, bm = blockIdx.y;

    float acc[4][4][4];
    gemm_mainloop(sA, sB, g_ctx + (size_t)bm * 128 * 1024,
                  W + (size_t)bn * 128 * 1024, acc);

    const int tid = threadIdx.x;
    const int lane = tid & 31, wid = tid >> 5;
    const int wm = (wid & 1) * 64, wn = (wid >> 1) * 32;
    const int g = lane >> 2, c = lane & 3;

#pragma unroll
    for (int mf = 0; mf < 4; mf++) {
#pragma unroll
        for (int rr = 0; rr < 2; rr++) {
            int ri = bm * 128 + wm + mf * 16 + g + rr * 8;
#pragma unroll
            for (int nf = 0; nf < 4; nf++) {
                int n = bn * 128 + wn + nf * 8 + 2 * c;
                float2 v;
                v.x = acc[mf][nf][rr * 2 + 0] + bias[n]     + X[(size_t)ri * 1024 + n];
                v.y = acc[mf][nf][rr * 2 + 1] + bias[n + 1] + X[(size_t)ri * 1024 + n + 1];
                *(float2*)(g_y + (size_t)ri * 1024 + n) = v;
            }
        }
    }
}

// ---------------------------------------------------------------------------
// Flash attention, tf32 mma.sync with permuted-k fragments.
// Block = one (b,h) x 128 q-rows, 8 warps (16 rows each), 64-key tiles,
// cp.async double-buffered K and V^T. Q fragments hoisted to registers.
// S's C-fragment feeds PV's A-fragment directly (no P smem round-trip).
// Softmax is invariant to the per-batch "vol" constant -> market_info dropped.
// ---------------------------------------------------------------------------
#define AP 72   // attn smem pitch (floats)
__global__ __launch_bounds__(256) void attn_tf32()
{
    extern __shared__ float sm[];
    float* Qs = sm;                       // 128 x AP
    float* Ks = Qs + 128 * AP;            // 2 x 64 x AP  ([key][dh])
    float* Vt = Ks + 2 * 64 * AP;         // 2 x 64 x AP  ([dh][key])

    const int bh = blockIdx.y;            // 0..31
    const int bb = bh >> 4, h = bh & 15;
    const int q0 = blockIdx.x * 128;
    const int tid = threadIdx.x;
    const int lane = tid & 31, w = tid >> 5;
    const int g = lane >> 2, c = lane & 3;

    const float* Qg  = g_q + ((size_t)bh * L_ + q0) * DH_;
    const float* Kg  = g_k + (size_t)bh * L_ * DH_;
    const float* VgT = g_v + (size_t)bh * DH_ * L_;   // [DH][L]

    // Load Q tile (128 x 64)
#pragma unroll
    for (int i = 0; i < 8; i++) {
        int f = tid + i * 256;            // 0..2047 float4s
        int r = f >> 4, c4 = f & 15;
        *(float4*)(Qs + r * AP + c4 * 4) =
            *(const float4*)(Qg + (size_t)r * 64 + c4 * 4);
    }

    // Prefetch K/V tile 0
#pragma unroll
    for (int i = 0; i < 4; i++) {
        int cidx = tid + i * 256;         // 0..1023
        int r = cidx >> 4, kc = cidx & 15;
        cpa16(Ks + r * AP + kc * 4, Kg + (size_t)r * 64 + kc * 4);
        cpa16(Vt + r * AP + kc * 4, VgT + (size_t)r * L_ + kc * 4);
    }
    CPA_COMMIT();
    __syncthreads();   // Q tile visible to all warps

    // Hoist Q fragments (permuted-k): constant across key tiles
    uint qa[8][4];
#pragma unroll
    for (int ks = 0; ks < 8; ks++) {
        float2 t0 = *(const float2*)(Qs + (w * 16 + g) * AP + ks * 8 + 2 * c);
        float2 t1 = *(const float2*)(Qs + (w * 16 + g + 8) * AP + ks * 8 + 2 * c);
        qa[ks][0] = __float_as_uint(t0.x);
        qa[ks][1] = __float_as_uint(t1.x);
        qa[ks][2] = __float_as_uint(t0.y);
        qa[ks][3] = __float_as_uint(t1.y);
    }

    float m0 = -1e30f, m1 = -1e30f, l0 = 0.f, l1 = 0.f;
    float o[8][4];
#pragma unroll
    for (int nf = 0; nf < 8; nf++)
#pragma unroll
        for (int r = 0; r < 4; r++) o[nf][r] = 0.f;

    for (int kt = 0; kt < L_ / 64; kt++) {
        const int s = kt & 1;
        if (kt + 1 < L_ / 64) {
            const float* Kt  = Kg  + (size_t)(kt + 1) * 64 * 64;
            const float* Vtg = VgT + (size_t)(kt + 1) * 64;
            float* Kd = Ks + ((kt + 1) & 1) * 64 * AP;
            float* Vd = Vt + ((kt + 1) & 1) * 64 * AP;
#pragma unroll
            for (int i = 0; i < 4; i++) {
                int cidx = tid + i * 256;
                int r = cidx >> 4, kc = cidx & 15;
                cpa16(Kd + r * AP + kc * 4, Kt + (size_t)r * 64 + kc * 4);
                cpa16(Vd + r * AP + kc * 4, Vtg + (size_t)r * L_ + kc * 4);
            }
            CPA_COMMIT();
            CPA_WAIT1();
        } else {
            CPA_WAIT0();
        }
        __syncthreads();
        const float* Ku = Ks + s * 64 * AP;
        const float* Vu = Vt + s * 64 * AP;

        // --- S = Q @ K^T (warp tile 16 x 64), permuted-k LDS.64 b-frags ---
        float sc[8][4];
#pragma unroll
        for (int nf = 0; nf < 8; nf++)
#pragma unroll
            for (int r = 0; r < 4; r++) sc[nf][r] = 0.f;
#pragma unroll
        for (int ks = 0; ks < 8; ks++) {
#pragma unroll
            for (int nf = 0; nf < 8; nf++) {
                float2 kb = *(const float2*)(Ku + (nf * 8 + g) * AP + ks * 8 + 2 * c);
                mma_tf32(sc[nf][0], sc[nf][1], sc[nf][2], sc[nf][3],
                         qa[ks][0], qa[ks][1], qa[ks][2], qa[ks][3],
                         __float_as_uint(kb.x), __float_as_uint(kb.y));
            }
        }

        // --- online softmax (rows g / g+8) ---
        float mx0 = -1e30f, mx1 = -1e30f;
#pragma unroll
        for (int nf = 0; nf < 8; nf++) {
#pragma unroll
            for (int r = 0; r < 4; r++) sc[nf][r] *= 0.125f;
            mx0 = fmaxf(mx0, fmaxf(sc[nf][0], sc[nf][1]));
            mx1 = fmaxf(mx1, fmaxf(sc[nf][2], sc[nf][3]));
        }
        mx0 = fmaxf(mx0, __shfl_xor_sync(0xffffffffu, mx0, 1));
        mx0 = fmaxf(mx0, __shfl_xor_sync(0xffffffffu, mx0, 2));
        mx1 = fmaxf(mx1, __shfl_xor_sync(0xffffffffu, mx1, 1));
        mx1 = fmaxf(mx1, __shfl_xor_sync(0xffffffffu, mx1, 2));
        float mn0 = fmaxf(m0, mx0), mn1 = fmaxf(m1, mx1);
        float al0 = __expf(m0 - mn0), al1 = __expf(m1 - mn1);
        float ls0 = 0.f, ls1 = 0.f;
#pragma unroll
        for (int nf = 0; nf < 8; nf++) {
            sc[nf][0] = __expf(sc[nf][0] - mn0);
            sc[nf][1] = __expf(sc[nf][1] - mn0);
            sc[nf][2] = __expf(sc[nf][2] - mn1);
            sc[nf][3] = __expf(sc[nf][3] - mn1);
            ls0 += sc[nf][0] + sc[nf][1];
            ls1 += sc[nf][2] + sc[nf][3];
        }
        ls0 += __shfl_xor_sync(0xffffffffu, ls0, 1);
        ls0 += __shfl_xor_sync(0xffffffffu, ls0, 2);
        ls1 += __shfl_xor_sync(0xffffffffu, ls1, 1);
        ls1 += __shfl_xor_sync(0xffffffffu, ls1, 2);
        l0 = l0 * al0 + ls0; m0 = mn0;
        l1 = l1 * al1 + ls1; m1 = mn1;
#pragma unroll
        for (int nf = 0; nf < 8; nf++) {
            o[nf][0] *= al0; o[nf][1] *= al0;
            o[nf][2] *= al1; o[nf][3] *= al1;
        }

        // --- O += P @ V: S's C-fragment IS the A-fragment under sigma ---
#pragma unroll
        for (int ks = 0; ks < 8; ks++) {
            uint p0 = __float_as_uint(sc[ks][0]);
            uint p1 = __float_as_uint(sc[ks][2]);
            uint p2 = __float_as_uint(sc[ks][1]);
            uint p3 = __float_as_uint(sc[ks][3]);
#pragma unroll
            for (int nf = 0; nf < 8; nf++) {
                float2 vb = *(const float2*)(Vu + (nf * 8 + g) * AP + ks * 8 + 2 * c);
                mma_tf32(o[nf][0], o[nf][1], o[nf][2], o[nf][3],
                         p0, p1, p2, p3,
                         __float_as_uint(vb.x), __float_as_uint(vb.y));
            }
        }
        __syncthreads();   // all warps done with this K/V buffer
    }

    // Epilogue: write ctx, layout [B,L,H*DH]
    float inv0 = 1.0f / l0, inv1 = 1.0f / l1;
    int r0 = q0 + w * 16 + g;
    int r1 = r0 + 8;
#pragma unroll
    for (int nf = 0; nf < 8; nf++) {
        int col = h * 64 + nf * 8 + 2 * c;
        float2 u0, u1;
        u0.x = o[nf][0] * inv0; u0.y = o[nf][1] * inv0;
        u1.x = o[nf][2] * inv1; u1.y = o[nf][3] * inv1;
        *(float2*)(g_ctx + ((size_t)(bb * L_ + r0)) * 1024 + col) = u0;
        *(float2*)(g_ctx + ((size_t)(bb * L_ + r1)) * 1024 + col) = u1;
    }
}

// ---------------------------------------------------------------------------
// LayerNorm over last dim (1024), one block per token row
// ---------------------------------------------------------------------------
__global__ __launch_bounds__(256) void ln_kernel(
    const float* __restrict__ gamma,
    const float* __restrict__ beta,
    float* __restrict__ out)
{
    const int row = blockIdx.x;
    const float* yr = g_y + (size_t)row * 1024;
    const int tid = threadIdx.x;

    float s = 0.f, sq = 0.f;
#pragma unroll
    for (int i = tid; i < 1024; i += 256) {
        float v = yr[i];
        s += v;
        sq += v * v;
    }
#pragma unroll
    for (int off = 16; off > 0; off >>= 1) {
        s  += __shfl_xor_sync(0xffffffffu, s, off);
        sq += __shfl_xor_sync(0xffffffffu, sq, off);
    }
    __shared__ float ws[8], wq[8];
    __shared__ float mu_s, rstd_s;
    int w = tid >> 5;
    if ((tid & 31) == 0) { ws[w] = s; wq[w] = sq; }
    __syncthreads();
    if (tid == 0) {
        float S = 0.f, Q = 0.f;
#pragma unroll
        for (int i = 0; i < 8; i++) { S += ws[i]; Q += wq[i]; }
        float mu = S * (1.0f / 1024.0f);
        float var = Q * (1.0f / 1024.0f) - mu * mu;
        mu_s = mu;
        rstd_s = rsqrtf(var + 1e-5f);
    }
    __syncthreads();
    float mu = mu_s, rstd = rstd_s;
#pragma unroll
    for (int i = tid; i < 1024; i += 256) {
        out[(size_t)row * 1024 + i] = (yr[i] - mu) * rstd * gamma[i] + beta[i];
    }
}

// ---------------------------------------------------------------------------
extern "C" void kernel_launch(void* const* d_in, const int* in_sizes, int n_in,
                              void* d_out, int out_size)
{
    const float* x      = (const float*)d_in[0];
    // d_in[1] = market_info: softmax-invariant constant, unused
    const float* w_in   = (const float*)d_in[2];
    const float* b_in   = (const float*)d_in[3];
    const float* w_out  = (const float*)d_in[4];
    const float* b_out  = (const float*)d_in[5];
    const float* gamma  = (const float*)d_in[6];
    const float* beta   = (const float*)d_in[7];
    float* out = (float*)d_out;

    // GEMM smem: 2 buffers x (A + B) x 128 x 40 floats = 81920 B
    const int gemm_smem = 4 * 128 * GP * (int)sizeof(float);
    cudaFuncSetAttribute(qkv_gemm, cudaFuncAttributeMaxDynamicSharedMemorySize, gemm_smem);
    cudaFuncSetAttribute(out_gemm, cudaFuncAttributeMaxDynamicSharedMemorySize, gemm_smem);

    // QKV projection
    qkv_gemm<<<dim3(24, 32), 256, gemm_smem>>>(x, w_in, b_in);

    // Attention: smem = (128 + 2*64 + 2*64) * 72 floats = 110592 B
    const int attn_smem = 384 * AP * (int)sizeof(float);
    cudaFuncSetAttribute(attn_tf32, cudaFuncAttributeMaxDynamicSharedMemorySize,
                         attn_smem);
    attn_tf32<<<dim3(L_ / 128, B_ * H_), 256, attn_smem>>>();

    // Output projection + residual
    out_gemm<<<dim3(8, 32), 256, gemm_smem>>>(x, w_out, b_out);

    // LayerNorm
    ln_kernel<<<NT, 256>>>(gamma, beta, out);
}

// round 10
// speedup vs baseline: 6.1676x; 1.6261x over previous
#include <cuda_runtime.h>
#include <cuda_fp16.h>
#include <math.h>

// Problem constants
#define B_  2
#define L_  2048
#define D_  1024
#define H_  16
#define DH_ 64
#define NT  (B_*L_)          // 4096 tokens
#define ND  (B_*H_*L_*DH_)   // 4M elements per Q/K/V

typedef unsigned int uint;

// Scratch. g_v is [B,H,DH,L] (transposed), keys permuted within 16-blocks.
__device__ __half g_xh[NT * D_];
__device__ __half g_wih[3 * D_ * D_];
__device__ __half g_woh[D_ * D_];
__device__ __half g_q[ND];
__device__ __half g_k[ND];
__device__ __half g_v[ND];
__device__ __half g_ctx[NT * D_];
__device__ float  g_y[NT * D_];

// ---------------------------------------------------------------------------
// helpers
// ---------------------------------------------------------------------------
__device__ __forceinline__ void mma_f16(
    float& c0, float& c1, float& c2, float& c3,
    uint a0, uint a1, uint a2, uint a3, uint b0, uint b1)
{
    asm volatile(
        "mma.sync.aligned.m16n8k16.row.col.f32.f16.f16.f32 "
        "{%0,%1,%2,%3}, {%4,%5,%6,%7}, {%8,%9}, {%0,%1,%2,%3};"
        : "+f"(c0), "+f"(c1), "+f"(c2), "+f"(c3)
        : "r"(a0), "r"(a1), "r"(a2), "r"(a3), "r"(b0), "r"(b1));
}

__device__ __forceinline__ uint pack2(float lo, float hi) {
    __half2 h = __floats2half2_rn(lo, hi);
    return *reinterpret_cast<uint*>(&h);
}

__device__ __forceinline__ uint smem_u32(const void* p) {
    uint a;
    asm("{ .reg .u64 t; cvta.to.shared.u64 t, %1; cvt.u32.u64 %0, t; }"
        : "=r"(a) : "l"(p));
    return a;
}

__device__ __forceinline__ void cpa16(void* sdst, const void* gsrc) {
    uint d = smem_u32(sdst);
    asm volatile("cp.async.cg.shared.global [%0], [%1], 16;"
                 :: "r"(d), "l"(gsrc) : "memory");
}
#define CPA_COMMIT() asm volatile("cp.async.commit_group;" ::: "memory")
#define CPA_WAIT1()  asm volatile("cp.async.wait_group 1;" ::: "memory")
#define CPA_WAIT0()  asm volatile("cp.async.wait_group 0;" ::: "memory")

// ---------------------------------------------------------------------------
// Prep: one-time fp32 -> fp16 of x, W_in, W_out (vectorized, grid-stride-free)
// ---------------------------------------------------------------------------
#define NQ_X   (NT * D_ / 4)        // 1048576
#define NQ_WI  (3 * D_ * D_ / 4)    // 786432
#define NQ_WO  (D_ * D_ / 4)        // 262144
__global__ __launch_bounds__(256) void prep_kernel(
    const float* __restrict__ x,
    const float* __restrict__ wi,
    const float* __restrict__ wo)
{
    int q = blockIdx.x * 256 + threadIdx.x;
    const float* src; __half* dst; int off;
    if (q < NQ_X)              { src = x;  dst = g_xh;  off = q; }
    else if (q < NQ_X + NQ_WI) { src = wi; dst = g_wih; off = q - NQ_X; }
    else                       { src = wo; dst = g_woh; off = q - NQ_X - NQ_WI; }
    float4 v = ((const float4*)src)[off];
    uint2 u;
    u.x = pack2(v.x, v.y);
    u.y = pack2(v.z, v.w);
    ((uint2*)dst)[off] = u;
}

// ---------------------------------------------------------------------------
// GEMM mainloop: acc[128x128] += A[bm*128.., K=1024] @ W[bn*128..]^T  (fp16)
// cp.async double-buffered, k-stage 64 halves (128B/row), [m][k] smem,
// pitch 80 halves (LDS.64 fragments conflict-free per half-warp).
// m16n8k16 split-k pairs fetched from contiguous halves {4c..4c+3}:
// valid because A and B share the same implicit k-permutation.
// 256 threads, 8 warps (2m x 4n), warp tile 64x32.
// ---------------------------------------------------------------------------
#define GP 80   // gemm smem pitch (halves)

__device__ __forceinline__ void gemm_copy_stage(
    __half* As, __half* Bs, const __half* Ab, const __half* Wb, int k0)
{
    const int tid = threadIdx.x;
#pragma unroll
    for (int i = 0; i < 4; i++) {
        int cidx = tid + i * 256;           // 0..1023
        int row = cidx >> 3, kc = cidx & 7; // 8 x 16B chunks per 64-half row
        cpa16(As + row * GP + kc * 8, Ab + (size_t)row * 1024 + k0 + kc * 8);
        cpa16(Bs + row * GP + kc * 8, Wb + (size_t)row * 1024 + k0 + kc * 8);
    }
}

__device__ __forceinline__ void gemm_mainloop(
    __half* sA, __half* sB, const __half* Ab, const __half* Wb, float acc[4][4][4])
{
    const int tid = threadIdx.x;
    const int lane = tid & 31, wid = tid >> 5;
    const int wm = (wid & 1) * 64, wn = (wid >> 1) * 32;
    const int g = lane >> 2, c = lane & 3;

#pragma unroll
    for (int mf = 0; mf < 4; mf++)
#pragma unroll
        for (int nf = 0; nf < 4; nf++)
#pragma unroll
            for (int r = 0; r < 4; r++) acc[mf][nf][r] = 0.f;

    gemm_copy_stage(sA, sB, Ab, Wb, 0);
    CPA_COMMIT();

    for (int it = 0; it < 16; it++) {
        const int s = it & 1;
        if (it + 1 < 16) {
            gemm_copy_stage(sA + ((it + 1) & 1) * (128 * GP),
                            sB + ((it + 1) & 1) * (128 * GP),
                            Ab, Wb, (it + 1) * 64);
            CPA_COMMIT();
            CPA_WAIT1();
        } else {
            CPA_WAIT0();
        }
        __syncthreads();
        const __half* A  = sA + s * (128 * GP);
        const __half* Bt = sB + s * (128 * GP);
#pragma unroll
        for (int ks = 0; ks < 4; ks++) {
            uint a[4][4], b[4][2];
#pragma unroll
            for (int mf = 0; mf < 4; mf++) {
                uint2 t0 = *(const uint2*)(A + (wm + mf * 16 + g) * GP + ks * 16 + 4 * c);
                uint2 t1 = *(const uint2*)(A + (wm + mf * 16 + g + 8) * GP + ks * 16 + 4 * c);
                a[mf][0] = t0.x; a[mf][1] = t1.x;
                a[mf][2] = t0.y; a[mf][3] = t1.y;
            }
#pragma unroll
            for (int nf = 0; nf < 4; nf++) {
                uint2 tb = *(const uint2*)(Bt + (wn + nf * 8 + g) * GP + ks * 16 + 4 * c);
                b[nf][0] = tb.x; b[nf][1] = tb.y;
            }
#pragma unroll
            for (int mf = 0; mf < 4; mf++)
#pragma unroll
                for (int nf = 0; nf < 4; nf++)
                    mma_f16(acc[mf][nf][0], acc[mf][nf][1], acc[mf][nf][2], acc[mf][nf][3],
                            a[mf][0], a[mf][1], a[mf][2], a[mf][3],
                            b[nf][0], b[nf][1]);
        }
        __syncthreads();
    }
}

// ---------------------------------------------------------------------------
// GEMM 1: qkv = x @ W_in^T + b_in; Q/K -> [B,H,L,DH] fp16,
// V -> [B,H,DH,L] fp16 with keys permuted per 16-block (PV LDS.64 layout).
// grid (24, 32), 256 threads
// ---------------------------------------------------------------------------
__global__ __launch_bounds__(256) void qkv_gemm(
    const float* __restrict__ bias)
{
    extern __shared__ __half smem[];
    __half* sA = smem;
    __half* sB = smem + 2 * 128 * GP;
    const int bn = blockIdx.x, bm = blockIdx.y;

    float acc[4][4][4];
    gemm_mainloop(sA, sB, g_xh + (size_t)bm * 128 * 1024,
                  g_wih + (size_t)bn * 128 * 1024, acc);

    const int tid = threadIdx.x;
    const int lane = tid & 31, wid = tid >> 5;
    const int wm = (wid & 1) * 64, wn = (wid >> 1) * 32;
    const int g = lane >> 2, c = lane & 3;
    const int part = (bn * 128) >> 10;       // uniform per CTA: 0=Q 1=K 2=V

#pragma unroll
    for (int mf = 0; mf < 4; mf++) {
#pragma unroll
        for (int rr = 0; rr < 2; rr++) {
            int ri = bm * 128 + wm + mf * 16 + g + rr * 8;
            int bb = ri >> 11, l = ri & 2047;
#pragma unroll
            for (int nf = 0; nf < 4; nf++) {
                int n = bn * 128 + wn + nf * 8 + 2 * c;
                float vx = acc[mf][nf][rr * 2 + 0] + bias[n];
                float vy = acc[mf][nf][rr * 2 + 1] + bias[n + 1];
                int hd = n & 1023;
                int h = hd >> 6, dh = hd & 63;
                if (part == 2) {
                    // V transposed [B,H,DH,L], key permuted within 16-block:
                    // logical offset o -> physical pos so PV b-frag is LDS.64
                    int o = l & 15;
                    int pos = (o < 8) ? (((o >> 1) << 2) | (o & 1))
                                      : ((((o - 8) >> 1) << 2) + 2 + (o & 1));
                    int lp = (l & ~15) | pos;
                    size_t base = ((size_t)(bb * H_ + h) * DH_ + dh) * L_ + lp;
                    g_v[base]      = __float2half_rn(vx);
                    g_v[base + L_] = __float2half_rn(vy);
                } else {
                    size_t dst = ((size_t)(bb * H_ + h) * L_ + l) * DH_ + dh;
                    __half2 hv = __floats2half2_rn(vx, vy);
                    *(__half2*)((part == 0 ? g_q : g_k) + dst) = hv;
                }
            }
        }
    }
}

// ---------------------------------------------------------------------------
// GEMM 2: y = x + ctx @ W_out^T + b_out ; grid (8, 32), 256 threads
// ---------------------------------------------------------------------------
__global__ __launch_bounds__(256) void out_gemm(
    const float* __restrict__ X,
    const float* __restrict__ bias)
{
    extern __shared__ __half smem[];
    __half* sA = smem;
    __half* sB = smem + 2 * 128 * GP;
    const int bn = blockIdx.x, bm = blockIdx.y;

    float acc[4][4][4];
    gemm_mainloop(sA, sB, g_ctx + (size_t)bm * 128 * 1024,
                  g_woh + (size_t)bn * 128 * 1024, acc);

    const int tid = threadIdx.x;
    const int lane = tid & 31, wid = tid >> 5;
    const int wm = (wid & 1) * 64, wn = (wid >> 1) * 32;
    const int g = lane >> 2, c = lane & 3;

#pragma unroll
    for (int mf = 0; mf < 4; mf++) {
#pragma unroll
        for (int rr = 0; rr < 2; rr++) {
            int ri = bm * 128 + wm + mf * 16 + g + rr * 8;
#pragma unroll
            for (int nf = 0; nf < 4; nf++) {
                int n = bn * 128 + wn + nf * 8 + 2 * c;
                float2 v;
                v.x = acc[mf][nf][rr * 2 + 0] + bias[n]     + X[(size_t)ri * 1024 + n];
                v.y = acc[mf][nf][rr * 2 + 1] + bias[n + 1] + X[(size_t)ri * 1024 + n + 1];
                *(float2*)(g_y + (size_t)ri * 1024 + n) = v;
            }
        }
    }
}

// ---------------------------------------------------------------------------
// Flash attention, fp16 mma.sync m16n8k16.
// Block = one (b,h) x 128 q-rows, 8 warps (16 rows each), 64-key tiles,
// cp.async double-buffered K and permuted V^T. Q fragments hoisted.
// S's fp32 C-fragment packs directly into PV's fp16 A-fragment.
// Softmax is invariant to the per-batch "vol" constant -> market_info dropped.
// ---------------------------------------------------------------------------
#define AP 80   // attn smem pitch (halves)
__global__ __launch_bounds__(256) void attn_f16()
{
    extern __shared__ __half sm[];
    __half* Qs = sm;                      // 128 x AP
    __half* Ks = Qs + 128 * AP;           // 2 x 64 x AP  ([key][dh])
    __half* Vs = Ks + 2 * 64 * AP;        // 2 x 64 x AP  ([dh][key-permuted])

    const int bh = blockIdx.y;            // 0..31
    const int bb = bh >> 4, h = bh & 15;
    const int q0 = blockIdx.x * 128;
    const int tid = threadIdx.x;
    const int lane = tid & 31, w = tid >> 5;
    const int g = lane >> 2, c = lane & 3;

    const __half* Qg  = g_q + ((size_t)bh * L_ + q0) * DH_;
    const __half* Kg  = g_k + (size_t)bh * L_ * DH_;
    const __half* VgT = g_v + (size_t)bh * DH_ * L_;   // [DH][L]

    // Q tile (128 x 64 halves) via cp.async
#pragma unroll
    for (int i = 0; i < 4; i++) {
        int cidx = tid + i * 256;         // 0..1023
        int r = cidx >> 3, kc = cidx & 7;
        cpa16(Qs + r * AP + kc * 8, Qg + (size_t)r * 64 + kc * 8);
    }
    // K/V tile 0 into buffer 0 (same commit group as Q)
#pragma unroll
    for (int i = 0; i < 2; i++) {
        int cidx = tid + i * 256;         // 0..511
        int r = cidx >> 3, kc = cidx & 7;
        cpa16(Ks + r * AP + kc * 8, Kg + (size_t)r * 64 + kc * 8);
        cpa16(Vs + r * AP + kc * 8, VgT + (size_t)r * L_ + kc * 8);
    }
    CPA_COMMIT();
    // K/V tile 1 into buffer 1
#pragma unroll
    for (int i = 0; i < 2; i++) {
        int cidx = tid + i * 256;
        int r = cidx >> 3, kc = cidx & 7;
        cpa16(Ks + 64 * AP + r * AP + kc * 8, Kg + (size_t)(64 + r) * 64 + kc * 8);
        cpa16(Vs + 64 * AP + r * AP + kc * 8, VgT + (size_t)r * L_ + 64 + kc * 8);
    }
    CPA_COMMIT();
    CPA_WAIT1();                          // Q + tile 0 resident
    __syncthreads();

    // Hoist Q fragments: constant across key tiles
    uint qa[4][4];
#pragma unroll
    for (int ks = 0; ks < 4; ks++) {
        uint2 t0 = *(const uint2*)(Qs + (w * 16 + g) * AP + ks * 16 + 4 * c);
        uint2 t1 = *(const uint2*)(Qs + (w * 16 + g + 8) * AP + ks * 16 + 4 * c);
        qa[ks][0] = t0.x; qa[ks][1] = t1.x;
        qa[ks][2] = t0.y; qa[ks][3] = t1.y;
    }

    float m0 = -1e30f, m1 = -1e30f, l0 = 0.f, l1 = 0.f;
    float o[8][4];
#pragma unroll
    for (int nf = 0; nf < 8; nf++)
#pragma unroll
        for (int r = 0; r < 4; r++) o[nf][r] = 0.f;

    const int NTILE = L_ / 64;            // 32
    for (int kt = 0; kt < NTILE; kt++) {
        const int s = kt & 1;
        const __half* Ku = Ks + s * 64 * AP;
        const __half* Vu = Vs + s * 64 * AP;

        // --- S = Q @ K^T (warp tile 16 x 64) ---
        float sc[8][4];
#pragma unroll
        for (int nf = 0; nf < 8; nf++)
#pragma unroll
            for (int r = 0; r < 4; r++) sc[nf][r] = 0.f;
#pragma unroll
        for (int ks = 0; ks < 4; ks++) {
#pragma unroll
            for (int nf = 0; nf < 8; nf++) {
                uint2 kb = *(const uint2*)(Ku + (nf * 8 + g) * AP + ks * 16 + 4 * c);
                mma_f16(sc[nf][0], sc[nf][1], sc[nf][2], sc[nf][3],
                        qa[ks][0], qa[ks][1], qa[ks][2], qa[ks][3],
                        kb.x, kb.y);
            }
        }

        // --- online softmax (rows g / g+8) ---
        float mx0 = -1e30f, mx1 = -1e30f;
#pragma unroll
        for (int nf = 0; nf < 8; nf++) {
#pragma unroll
            for (int r = 0; r < 4; r++) sc[nf][r] *= 0.125f;
            mx0 = fmaxf(mx0, fmaxf(sc[nf][0], sc[nf][1]));
            mx1 = fmaxf(mx1, fmaxf(sc[nf][2], sc[nf][3]));
        }
        mx0 = fmaxf(mx0, __shfl_xor_sync(0xffffffffu, mx0, 1));
        mx0 = fmaxf(mx0, __shfl_xor_sync(0xffffffffu, mx0, 2));
        mx1 = fmaxf(mx1, __shfl_xor_sync(0xffffffffu, mx1, 1));
        mx1 = fmaxf(mx1, __shfl_xor_sync(0xffffffffu, mx1, 2));
        float mn0 = fmaxf(m0, mx0), mn1 = fmaxf(m1, mx1);
        float al0 = __expf(m0 - mn0), al1 = __expf(m1 - mn1);
        float ls0 = 0.f, ls1 = 0.f;
#pragma unroll
        for (int nf = 0; nf < 8; nf++) {
            sc[nf][0] = __expf(sc[nf][0] - mn0);
            sc[nf][1] = __expf(sc[nf][1] - mn0);
            sc[nf][2] = __expf(sc[nf][2] - mn1);
            sc[nf][3] = __expf(sc[nf][3] - mn1);
            ls0 += sc[nf][0] + sc[nf][1];
            ls1 += sc[nf][2] + sc[nf][3];
        }
        ls0 += __shfl_xor_sync(0xffffffffu, ls0, 1);
        ls0 += __shfl_xor_sync(0xffffffffu, ls0, 2);
        ls1 += __shfl_xor_sync(0xffffffffu, ls1, 1);
        ls1 += __shfl_xor_sync(0xffffffffu, ls1, 2);
        l0 = l0 * al0 + ls0; m0 = mn0;
        l1 = l1 * al1 + ls1; m1 = mn1;
#pragma unroll
        for (int nf = 0; nf < 8; nf++) {
            o[nf][0] *= al0; o[nf][1] *= al0;
            o[nf][2] *= al1; o[nf][3] *= al1;
        }

        // --- O += P @ V: pack S's C-frag into fp16 A-frag ---
#pragma unroll
        for (int t = 0; t < 4; t++) {
            uint a0 = pack2(sc[2 * t][0],     sc[2 * t][1]);
            uint a1 = pack2(sc[2 * t][2],     sc[2 * t][3]);
            uint a2 = pack2(sc[2 * t + 1][0], sc[2 * t + 1][1]);
            uint a3 = pack2(sc[2 * t + 1][2], sc[2 * t + 1][3]);
#pragma unroll
            for (int nf = 0; nf < 8; nf++) {
                uint2 vb = *(const uint2*)(Vu + (nf * 8 + g) * AP + t * 16 + 4 * c);
                mma_f16(o[nf][0], o[nf][1], o[nf][2], o[nf][3],
                        a0, a1, a2, a3, vb.x, vb.y);
            }
        }

        // prefetch kt+2 into this buffer, wait for kt+1
        __syncthreads();                   // all warps done reading buffer s
        if (kt + 2 < NTILE) {
            const __half* Kt  = Kg  + (size_t)(kt + 2) * 64 * 64;
            const __half* Vtg = VgT + (size_t)(kt + 2) * 64;
            __half* Kd = Ks + s * 64 * AP;
            __half* Vd = Vs + s * 64 * AP;
#pragma unroll
            for (int i = 0; i < 2; i++) {
                int cidx = tid + i * 256;
                int r = cidx >> 3, kc = cidx & 7;
                cpa16(Kd + r * AP + kc * 8, Kt + (size_t)r * 64 + kc * 8);
                cpa16(Vd + r * AP + kc * 8, Vtg + (size_t)r * L_ + kc * 8);
            }
            CPA_COMMIT();
            CPA_WAIT1();
        } else {
            CPA_WAIT0();
        }
        __syncthreads();                   // kt+1 data visible to all warps
    }

    // Epilogue: write ctx fp16, layout [B,L,H*DH]
    float inv0 = 1.0f / l0, inv1 = 1.0f / l1;
    int r0 = q0 + w * 16 + g;
    int r1 = r0 + 8;
#pragma unroll
    for (int nf = 0; nf < 8; nf++) {
        int col = h * 64 + nf * 8 + 2 * c;
        __half2 u0 = __floats2half2_rn(o[nf][0] * inv0, o[nf][1] * inv0);
        __half2 u1 = __floats2half2_rn(o[nf][2] * inv1, o[nf][3] * inv1);
        *(__half2*)(g_ctx + (size_t)(bb * L_ + r0) * 1024 + col) = u0;
        *(__half2*)(g_ctx + (size_t)(bb * L_ + r1) * 1024 + col) = u1;
    }
}

// ---------------------------------------------------------------------------
// LayerNorm over last dim (1024), one block per token row
// ---------------------------------------------------------------------------
__global__ __launch_bounds__(256) void ln_kernel(
    const float* __restrict__ gamma,
    const float* __restrict__ beta,
    float* __restrict__ out)
{
    const int row = blockIdx.x;
    const float* yr = g_y + (size_t)row * 1024;
    const int tid = threadIdx.x;

    float s = 0.f, sq = 0.f;
#pragma unroll
    for (int i = tid; i < 1024; i += 256) {
        float v = yr[i];
        s += v;
        sq += v * v;
    }
#pragma unroll
    for (int off = 16; off > 0; off >>= 1) {
        s  += __shfl_xor_sync(0xffffffffu, s, off);
        sq += __shfl_xor_sync(0xffffffffu, sq, off);
    }
    __shared__ float ws[8], wq[8];
    __shared__ float mu_s, rstd_s;
    int w = tid >> 5;
    if ((tid & 31) == 0) { ws[w] = s; wq[w] = sq; }
    __syncthreads();
    if (tid == 0) {
        float S = 0.f, Q = 0.f;
#pragma unroll
        for (int i = 0; i < 8; i++) { S += ws[i]; Q += wq[i]; }
        float mu = S * (1.0f / 1024.0f);
        float var = Q * (1.0f / 1024.0f) - mu * mu;
        mu_s = mu;
        rstd_s = rsqrtf(var + 1e-5f);
    }
    __syncthreads();
    float mu = mu_s, rstd = rstd_s;
#pragma unroll
    for (int i = tid; i < 1024; i += 256) {
        out[(size_t)row * 1024 + i] = (yr[i] - mu) * rstd * gamma[i] + beta[i];
    }
}

// ---------------------------------------------------------------------------
extern "C" void kernel_launch(void* const* d_in, const int* in_sizes, int n_in,
                              void* d_out, int out_size)
{
    const float* x      = (const float*)d_in[0];
    // d_in[1] = market_info: softmax-invariant constant, unused
    const float* w_in   = (const float*)d_in[2];
    const float* b_in   = (const float*)d_in[3];
    const float* w_out  = (const float*)d_in[4];
    const float* b_out  = (const float*)d_in[5];
    const float* gamma  = (const float*)d_in[6];
    const float* beta   = (const float*)d_in[7];
    float* out = (float*)d_out;

    // fp32 -> fp16 prep (x, W_in, W_out)
    prep_kernel<<<(NQ_X + NQ_WI + NQ_WO) / 256, 256>>>(x, w_in, w_out);

    // GEMM smem: 2 buffers x (A + B) x 128 x 80 halves = 81920 B
    const int gemm_smem = 4 * 128 * GP * (int)sizeof(__half);
    cudaFuncSetAttribute(qkv_gemm, cudaFuncAttributeMaxDynamicSharedMemorySize, gemm_smem);
    cudaFuncSetAttribute(out_gemm, cudaFuncAttributeMaxDynamicSharedMemorySize, gemm_smem);

    // QKV projection
    qkv_gemm<<<dim3(24, 32), 256, gemm_smem>>>(b_in);

    // Attention: smem = (128 + 2*64 + 2*64) * 80 halves = 61440 B
    const int attn_smem = 384 * AP * (int)sizeof(__half);
    cudaFuncSetAttribute(attn_f16, cudaFuncAttributeMaxDynamicSharedMemorySize,
                         attn_smem);
    attn_f16<<<dim3(L_ / 128, B_ * H_), 256, attn_smem>>>();

    // Output projection + residual
    out_gemm<<<dim3(8, 32), 256, gemm_smem>>>(x, b_out);

    // LayerNorm
    ln_kernel<<<NT, 256>>>(gamma, beta, out);
}

// round 14
// speedup vs baseline: 6.8397x; 1.1090x over previous
#include <cuda_runtime.h>
#include <cuda_fp16.h>
#include <math.h>

// Problem constants
#define B_  2
#define L_  2048
#define D_  1024
#define H_  16
#define DH_ 64
#define NT  (B_*L_)          // 4096 tokens
#define ND  (B_*H_*L_*DH_)   // 4M elements per Q/K/V

typedef unsigned int uint;

// Scratch. g_v is [B,H,DH,L] (transposed), keys permuted within 16-blocks.
__device__ __half g_xh[NT * D_];
__device__ __half g_wih[3 * D_ * D_];
__device__ __half g_woh[D_ * D_];
__device__ __half g_q[ND];
__device__ __half g_k[ND];
__device__ __half g_v[ND];
__device__ __half g_ctx[NT * D_];
__device__ float  g_y[NT * D_];

// ---------------------------------------------------------------------------
// helpers
// ---------------------------------------------------------------------------
__device__ __forceinline__ void mma_f16(
    float& c0, float& c1, float& c2, float& c3,
    uint a0, uint a1, uint a2, uint a3, uint b0, uint b1)
{
    asm volatile(
        "mma.sync.aligned.m16n8k16.row.col.f32.f16.f16.f32 "
        "{%0,%1,%2,%3}, {%4,%5,%6,%7}, {%8,%9}, {%0,%1,%2,%3};"
        : "+f"(c0), "+f"(c1), "+f"(c2), "+f"(c3)
        : "r"(a0), "r"(a1), "r"(a2), "r"(a3), "r"(b0), "r"(b1));
}

__device__ __forceinline__ uint pack2(float lo, float hi) {
    __half2 h = __floats2half2_rn(lo, hi);
    return *reinterpret_cast<uint*>(&h);
}

__device__ __forceinline__ uint smem_u32(const void* p) {
    uint a;
    asm("{ .reg .u64 t; cvta.to.shared.u64 t, %1; cvt.u32.u64 %0, t; }"
        : "=r"(a) : "l"(p));
    return a;
}

__device__ __forceinline__ void cpa16(void* sdst, const void* gsrc) {
    uint d = smem_u32(sdst);
    asm volatile("cp.async.cg.shared.global [%0], [%1], 16;"
                 :: "r"(d), "l"(gsrc) : "memory");
}
#define CPA_COMMIT() asm volatile("cp.async.commit_group;" ::: "memory")
#define CPA_WAIT1()  asm volatile("cp.async.wait_group 1;" ::: "memory")
#define CPA_WAIT0()  asm volatile("cp.async.wait_group 0;" ::: "memory")

// ---------------------------------------------------------------------------
// Prep: one-time fp32 -> fp16 of x, W_in, W_out
// ---------------------------------------------------------------------------
#define NQ_X   (NT * D_ / 4)        // 1048576
#define NQ_WI  (3 * D_ * D_ / 4)    // 786432
#define NQ_WO  (D_ * D_ / 4)        // 262144
__global__ __launch_bounds__(256) void prep_kernel(
    const float* __restrict__ x,
    const float* __restrict__ wi,
    const float* __restrict__ wo)
{
    int q = blockIdx.x * 256 + threadIdx.x;
    const float* src; __half* dst; int off;
    if (q < NQ_X)              { src = x;  dst = g_xh;  off = q; }
    else if (q < NQ_X + NQ_WI) { src = wi; dst = g_wih; off = q - NQ_X; }
    else                       { src = wo; dst = g_woh; off = q - NQ_X - NQ_WI; }
    float4 v = ((const float4*)src)[off];
    uint2 u;
    u.x = pack2(v.x, v.y);
    u.y = pack2(v.z, v.w);
    ((uint2*)dst)[off] = u;
}

// ---------------------------------------------------------------------------
// GEMM mainloop: acc[128x128] += A[bm*128.., K=1024] @ W[bn*128..]^T  (fp16)
// 128 threads, 4 warps (2m x 2n), warp tile 64x64: 32 HMMA per 16 LDS.64
// per k-step. cp.async double-buffered, k-stage 64 halves, pitch 80.
// 2 CTAs/SM (80KB smem each).
// ---------------------------------------------------------------------------
#define GP 80   // gemm smem pitch (halves)

__device__ __forceinline__ void gemm_copy_stage(
    __half* As, __half* Bs, const __half* Ab, const __half* Wb, int k0)
{
    const int tid = threadIdx.x;
#pragma unroll
    for (int i = 0; i < 8; i++) {
        int cidx = tid + i * 128;           // 0..1023
        int row = cidx >> 3, kc = cidx & 7; // 8 x 16B chunks per 64-half row
        cpa16(As + row * GP + kc * 8, Ab + (size_t)row * 1024 + k0 + kc * 8);
        cpa16(Bs + row * GP + kc * 8, Wb + (size_t)row * 1024 + k0 + kc * 8);
    }
}

__device__ __forceinline__ void gemm_mainloop(
    __half* sA, __half* sB, const __half* Ab, const __half* Wb, float acc[4][8][4])
{
    const int tid = threadIdx.x;
    const int lane = tid & 31, wid = tid >> 5;
    const int wm = (wid & 1) * 64, wn = (wid >> 1) * 64;
    const int g = lane >> 2, c = lane & 3;

#pragma unroll
    for (int mf = 0; mf < 4; mf++)
#pragma unroll
        for (int nf = 0; nf < 8; nf++)
#pragma unroll
            for (int r = 0; r < 4; r++) acc[mf][nf][r] = 0.f;

    gemm_copy_stage(sA, sB, Ab, Wb, 0);
    CPA_COMMIT();

    for (int it = 0; it < 16; it++) {
        const int s = it & 1;
        if (it + 1 < 16) {
            gemm_copy_stage(sA + ((it + 1) & 1) * (128 * GP),
                            sB + ((it + 1) & 1) * (128 * GP),
                            Ab, Wb, (it + 1) * 64);
            CPA_COMMIT();
            CPA_WAIT1();
        } else {
            CPA_WAIT0();
        }
        __syncthreads();
        const __half* A  = sA + s * (128 * GP);
        const __half* Bt = sB + s * (128 * GP);
#pragma unroll
        for (int ks = 0; ks < 4; ks++) {
            uint a[4][4], b[8][2];
#pragma unroll
            for (int mf = 0; mf < 4; mf++) {
                uint2 t0 = *(const uint2*)(A + (wm + mf * 16 + g) * GP + ks * 16 + 4 * c);
                uint2 t1 = *(const uint2*)(A + (wm + mf * 16 + g + 8) * GP + ks * 16 + 4 * c);
                a[mf][0] = t0.x; a[mf][1] = t1.x;
                a[mf][2] = t0.y; a[mf][3] = t1.y;
            }
#pragma unroll
            for (int nf = 0; nf < 8; nf++) {
                uint2 tb = *(const uint2*)(Bt + (wn + nf * 8 + g) * GP + ks * 16 + 4 * c);
                b[nf][0] = tb.x; b[nf][1] = tb.y;
            }
#pragma unroll
            for (int mf = 0; mf < 4; mf++)
#pragma unroll
                for (int nf = 0; nf < 8; nf++)
                    mma_f16(acc[mf][nf][0], acc[mf][nf][1], acc[mf][nf][2], acc[mf][nf][3],
                            a[mf][0], a[mf][1], a[mf][2], a[mf][3],
                            b[nf][0], b[nf][1]);
        }
        __syncthreads();
    }
}

// ---------------------------------------------------------------------------
// GEMM 1: qkv = x @ W_in^T + b_in; Q/K -> [B,H,L,DH] fp16,
// V -> [B,H,DH,L] fp16 with keys permuted per 16-block.
// grid (24, 32), 128 threads
// ---------------------------------------------------------------------------
__global__ __launch_bounds__(128) void qkv_gemm(
    const float* __restrict__ bias)
{
    extern __shared__ __half smem[];
    __half* sA = smem;
    __half* sB = smem + 2 * 128 * GP;
    const int bn = blockIdx.x, bm = blockIdx.y;

    float acc[4][8][4];
    gemm_mainloop(sA, sB, g_xh + (size_t)bm * 128 * 1024,
                  g_wih + (size_t)bn * 128 * 1024, acc);

    const int tid = threadIdx.x;
    const int lane = tid & 31, wid = tid >> 5;
    const int wm = (wid & 1) * 64, wn = (wid >> 1) * 64;
    const int g = lane >> 2, c = lane & 3;
    const int part = (bn * 128) >> 10;       // uniform per CTA: 0=Q 1=K 2=V

#pragma unroll
    for (int mf = 0; mf < 4; mf++) {
#pragma unroll
        for (int rr = 0; rr < 2; rr++) {
            int ri = bm * 128 + wm + mf * 16 + g + rr * 8;
            int bb = ri >> 11, l = ri & 2047;
#pragma unroll
            for (int nf = 0; nf < 8; nf++) {
                int n = bn * 128 + wn + nf * 8 + 2 * c;
                float vx = acc[mf][nf][rr * 2 + 0] + bias[n];
                float vy = acc[mf][nf][rr * 2 + 1] + bias[n + 1];
                int hd = n & 1023;
                int h = hd >> 6, dh = hd & 63;
                if (part == 2) {
                    // V transposed [B,H,DH,L], key permuted within 16-block
                    int o = l & 15;
                    int pos = (o < 8) ? (((o >> 1) << 2) | (o & 1))
                                      : ((((o - 8) >> 1) << 2) + 2 + (o & 1));
                    int lp = (l & ~15) | pos;
                    size_t base = ((size_t)(bb * H_ + h) * DH_ + dh) * L_ + lp;
                    g_v[base]      = __float2half_rn(vx);
                    g_v[base + L_] = __float2half_rn(vy);
                } else {
                    size_t dst = ((size_t)(bb * H_ + h) * L_ + l) * DH_ + dh;
                    __half2 hv = __floats2half2_rn(vx, vy);
                    *(__half2*)((part == 0 ? g_q : g_k) + dst) = hv;
                }
            }
        }
    }
}

// ---------------------------------------------------------------------------
// GEMM 2: y = x + ctx @ W_out^T + b_out ; grid (8, 32), 128 threads
// ---------------------------------------------------------------------------
__global__ __launch_bounds__(128) void out_gemm(
    const float* __restrict__ X,
    const float* __restrict__ bias)
{
    extern __shared__ __half smem[];
    __half* sA = smem;
    __half* sB = smem + 2 * 128 * GP;
    const int bn = blockIdx.x, bm = blockIdx.y;

    float acc[4][8][4];
    gemm_mainloop(sA, sB, g_ctx + (size_t)bm * 128 * 1024,
                  g_woh + (size_t)bn * 128 * 1024, acc);

    const int tid = threadIdx.x;
    const int lane = tid & 31, wid = tid >> 5;
    const int wm = (wid & 1) * 64, wn = (wid >> 1) * 64;
    const int g = lane >> 2, c = lane & 3;

#pragma unroll
    for (int mf = 0; mf < 4; mf++) {
#pragma unroll
        for (int rr = 0; rr < 2; rr++) {
            int ri = bm * 128 + wm + mf * 16 + g + rr * 8;
#pragma unroll
            for (int nf = 0; nf < 8; nf++) {
                int n = bn * 128 + wn + nf * 8 + 2 * c;
                float2 v;
                v.x = acc[mf][nf][rr * 2 + 0] + bias[n]     + X[(size_t)ri * 1024 + n];
                v.y = acc[mf][nf][rr * 2 + 1] + bias[n + 1] + X[(size_t)ri * 1024 + n + 1];
                *(float2*)(g_y + (size_t)ri * 1024 + n) = v;
            }
        }
    }
}

// ---------------------------------------------------------------------------
// Flash attention, fp16 mma.sync. 128 threads, 4 warps; each warp owns
// 32 q-rows (two 16-row halves). K/V b-fragments loaded ONCE per (ks,nf)
// and shared by both halves' MMAs -> LDS per tile halves vs R10.
// cp.async double-buffered K and permuted V^T. Q fragments hoisted.
// Softmax is invariant to the per-batch "vol" constant -> market_info dropped.
// ---------------------------------------------------------------------------
#define AP 80   // attn smem pitch (halves)
__global__ __launch_bounds__(128) void attn_f16()
{
    extern __shared__ __half sm[];
    __half* Qs = sm;                      // 128 x AP
    __half* Ks = Qs + 128 * AP;           // 2 x 64 x AP  ([key][dh])
    __half* Vs = Ks + 2 * 64 * AP;        // 2 x 64 x AP  ([dh][key-permuted])

    const int bh = blockIdx.y;            // 0..31
    const int bb = bh >> 4, h = bh & 15;
    const int q0 = blockIdx.x * 128;
    const int tid = threadIdx.x;
    const int lane = tid & 31, w = tid >> 5;   // w: 0..3
    const int g = lane >> 2, c = lane & 3;

    const __half* Qg  = g_q + ((size_t)bh * L_ + q0) * DH_;
    const __half* Kg  = g_k + (size_t)bh * L_ * DH_;
    const __half* VgT = g_v + (size_t)bh * DH_ * L_;   // [DH][L]

    // Q tile (128 x 64 halves)
#pragma unroll
    for (int i = 0; i < 8; i++) {
        int cidx = tid + i * 128;         // 0..1023
        int r = cidx >> 3, kc = cidx & 7;
        cpa16(Qs + r * AP + kc * 8, Qg + (size_t)r * 64 + kc * 8);
    }
    // K/V tile 0 -> buffer 0
#pragma unroll
    for (int i = 0; i < 4; i++) {
        int cidx = tid + i * 128;         // 0..511
        int r = cidx >> 3, kc = cidx & 7;
        cpa16(Ks + r * AP + kc * 8, Kg + (size_t)r * 64 + kc * 8);
        cpa16(Vs + r * AP + kc * 8, VgT + (size_t)r * L_ + kc * 8);
    }
    CPA_COMMIT();
    // K/V tile 1 -> buffer 1
#pragma unroll
    for (int i = 0; i < 4; i++) {
        int cidx = tid + i * 128;
        int r = cidx >> 3, kc = cidx & 7;
        cpa16(Ks + 64 * AP + r * AP + kc * 8, Kg + (size_t)(64 + r) * 64 + kc * 8);
        cpa16(Vs + 64 * AP + r * AP + kc * 8, VgT + (size_t)r * L_ + 64 + kc * 8);
    }
    CPA_COMMIT();
    CPA_WAIT1();                          // Q + tile 0 resident
    __syncthreads();

    // Hoist Q fragments for both 16-row halves
    uint qa[2][4][4];
#pragma unroll
    for (int hm = 0; hm < 2; hm++) {
#pragma unroll
        for (int ks = 0; ks < 4; ks++) {
            uint2 t0 = *(const uint2*)(Qs + (w * 32 + hm * 16 + g) * AP + ks * 16 + 4 * c);
            uint2 t1 = *(const uint2*)(Qs + (w * 32 + hm * 16 + g + 8) * AP + ks * 16 + 4 * c);
            qa[hm][ks][0] = t0.x; qa[hm][ks][1] = t1.x;
            qa[hm][ks][2] = t0.y; qa[hm][ks][3] = t1.y;
        }
    }

    float m[4], l[4];
#pragma unroll
    for (int i = 0; i < 4; i++) { m[i] = -1e30f; l[i] = 0.f; }
    float o[2][8][4];
#pragma unroll
    for (int hm = 0; hm < 2; hm++)
#pragma unroll
        for (int nf = 0; nf < 8; nf++)
#pragma unroll
            for (int r = 0; r < 4; r++) o[hm][nf][r] = 0.f;

    const int NTILE = L_ / 64;            // 32
    for (int kt = 0; kt < NTILE; kt++) {
        const int s = kt & 1;
        const __half* Ku = Ks + s * 64 * AP;
        const __half* Vu = Vs + s * 64 * AP;

        // --- S = Q @ K^T: K frag loaded once, feeds both halves ---
        float sc[2][8][4];
#pragma unroll
        for (int hm = 0; hm < 2; hm++)
#pragma unroll
            for (int nf = 0; nf < 8; nf++)
#pragma unroll
                for (int r = 0; r < 4; r++) sc[hm][nf][r] = 0.f;
#pragma unroll
        for (int ks = 0; ks < 4; ks++) {
#pragma unroll
            for (int nf = 0; nf < 8; nf++) {
                uint2 kb = *(const uint2*)(Ku + (nf * 8 + g) * AP + ks * 16 + 4 * c);
                mma_f16(sc[0][nf][0], sc[0][nf][1], sc[0][nf][2], sc[0][nf][3],
                        qa[0][ks][0], qa[0][ks][1], qa[0][ks][2], qa[0][ks][3],
                        kb.x, kb.y);
                mma_f16(sc[1][nf][0], sc[1][nf][1], sc[1][nf][2], sc[1][nf][3],
                        qa[1][ks][0], qa[1][ks][1], qa[1][ks][2], qa[1][ks][3],
                        kb.x, kb.y);
            }
        }

        // --- online softmax per half (rows g / g+8) ---
#pragma unroll
        for (int hm = 0; hm < 2; hm++) {
            float mx0 = -1e30f, mx1 = -1e30f;
#pragma unroll
            for (int nf = 0; nf < 8; nf++) {
#pragma unroll
                for (int r = 0; r < 4; r++) sc[hm][nf][r] *= 0.125f;
                mx0 = fmaxf(mx0, fmaxf(sc[hm][nf][0], sc[hm][nf][1]));
                mx1 = fmaxf(mx1, fmaxf(sc[hm][nf][2], sc[hm][nf][3]));
            }
            mx0 = fmaxf(mx0, __shfl_xor_sync(0xffffffffu, mx0, 1));
            mx0 = fmaxf(mx0, __shfl_xor_sync(0xffffffffu, mx0, 2));
            mx1 = fmaxf(mx1, __shfl_xor_sync(0xffffffffu, mx1, 1));
            mx1 = fmaxf(mx1, __shfl_xor_sync(0xffffffffu, mx1, 2));
            float mn0 = fmaxf(m[hm * 2], mx0), mn1 = fmaxf(m[hm * 2 + 1], mx1);
            float al0 = __expf(m[hm * 2] - mn0), al1 = __expf(m[hm * 2 + 1] - mn1);
            float ls0 = 0.f, ls1 = 0.f;
#pragma unroll
            for (int nf = 0; nf < 8; nf++) {
                sc[hm][nf][0] = __expf(sc[hm][nf][0] - mn0);
                sc[hm][nf][1] = __expf(sc[hm][nf][1] - mn0);
                sc[hm][nf][2] = __expf(sc[hm][nf][2] - mn1);
                sc[hm][nf][3] = __expf(sc[hm][nf][3] - mn1);
                ls0 += sc[hm][nf][0] + sc[hm][nf][1];
                ls1 += sc[hm][nf][2] + sc[hm][nf][3];
            }
            ls0 += __shfl_xor_sync(0xffffffffu, ls0, 1);
            ls0 += __shfl_xor_sync(0xffffffffu, ls0, 2);
            ls1 += __shfl_xor_sync(0xffffffffu, ls1, 1);
            ls1 += __shfl_xor_sync(0xffffffffu, ls1, 2);
            l[hm * 2]     = l[hm * 2]     * al0 + ls0;  m[hm * 2]     = mn0;
            l[hm * 2 + 1] = l[hm * 2 + 1] * al1 + ls1;  m[hm * 2 + 1] = mn1;
#pragma unroll
            for (int nf = 0; nf < 8; nf++) {
                o[hm][nf][0] *= al0; o[hm][nf][1] *= al0;
                o[hm][nf][2] *= al1; o[hm][nf][3] *= al1;
            }
        }

        // --- O += P @ V: V frag loaded once, feeds both halves ---
#pragma unroll
        for (int t = 0; t < 4; t++) {
            uint a0[2], a1[2], a2[2], a3[2];
#pragma unroll
            for (int hm = 0; hm < 2; hm++) {
                a0[hm] = pack2(sc[hm][2 * t][0],     sc[hm][2 * t][1]);
                a1[hm] = pack2(sc[hm][2 * t][2],     sc[hm][2 * t][3]);
                a2[hm] = pack2(sc[hm][2 * t + 1][0], sc[hm][2 * t + 1][1]);
                a3[hm] = pack2(sc[hm][2 * t + 1][2], sc[hm][2 * t + 1][3]);
            }
#pragma unroll
            for (int nf = 0; nf < 8; nf++) {
                uint2 vb = *(const uint2*)(Vu + (nf * 8 + g) * AP + t * 16 + 4 * c);
                mma_f16(o[0][nf][0], o[0][nf][1], o[0][nf][2], o[0][nf][3],
                        a0[0], a1[0], a2[0], a3[0], vb.x, vb.y);
                mma_f16(o[1][nf][0], o[1][nf][1], o[1][nf][2], o[1][nf][3],
                        a0[1], a1[1], a2[1], a3[1], vb.x, vb.y);
            }
        }

        // prefetch kt+2 into this buffer, wait for kt+1
        __syncthreads();                   // all warps done reading buffer s
        if (kt + 2 < NTILE) {
            const __half* Kt  = Kg  + (size_t)(kt + 2) * 64 * 64;
            const __half* Vtg = VgT + (size_t)(kt + 2) * 64;
            __half* Kd = Ks + s * 64 * AP;
            __half* Vd = Vs + s * 64 * AP;
#pragma unroll
            for (int i = 0; i < 4; i++) {
                int cidx = tid + i * 128;
                int r = cidx >> 3, kc = cidx & 7;
                cpa16(Kd + r * AP + kc * 8, Kt + (size_t)r * 64 + kc * 8);
                cpa16(Vd + r * AP + kc * 8, Vtg + (size_t)r * L_ + kc * 8);
            }
            CPA_COMMIT();
            CPA_WAIT1();
        } else {
            CPA_WAIT0();
        }
        __syncthreads();                   // kt+1 data visible to all warps
    }

    // Epilogue: write ctx fp16, layout [B,L,H*DH]
#pragma unroll
    for (int hm = 0; hm < 2; hm++) {
        float inv0 = 1.0f / l[hm * 2], inv1 = 1.0f / l[hm * 2 + 1];
        int r0 = q0 + w * 32 + hm * 16 + g;
        int r1 = r0 + 8;
#pragma unroll
        for (int nf = 0; nf < 8; nf++) {
            int col = h * 64 + nf * 8 + 2 * c;
            __half2 u0 = __floats2half2_rn(o[hm][nf][0] * inv0, o[hm][nf][1] * inv0);
            __half2 u1 = __floats2half2_rn(o[hm][nf][2] * inv1, o[hm][nf][3] * inv1);
            *(__half2*)(g_ctx + (size_t)(bb * L_ + r0) * 1024 + col) = u0;
            *(__half2*)(g_ctx + (size_t)(bb * L_ + r1) * 1024 + col) = u1;
        }
    }
}

// ---------------------------------------------------------------------------
// LayerNorm over last dim (1024), one block per token row
// ---------------------------------------------------------------------------
__global__ __launch_bounds__(256) void ln_kernel(
    const float* __restrict__ gamma,
    const float* __restrict__ beta,
    float* __restrict__ out)
{
    const int row = blockIdx.x;
    const float* yr = g_y + (size_t)row * 1024;
    const int tid = threadIdx.x;

    float s = 0.f, sq = 0.f;
#pragma unroll
    for (int i = tid; i < 1024; i += 256) {
        float v = yr[i];
        s += v;
        sq += v * v;
    }
#pragma unroll
    for (int off = 16; off > 0; off >>= 1) {
        s  += __shfl_xor_sync(0xffffffffu, s, off);
        sq += __shfl_xor_sync(0xffffffffu, sq, off);
    }
    __shared__ float ws[8], wq[8];
    __shared__ float mu_s, rstd_s;
    int w = tid >> 5;
    if ((tid & 31) == 0) { ws[w] = s; wq[w] = sq; }
    __syncthreads();
    if (tid == 0) {
        float S = 0.f, Q = 0.f;
#pragma unroll
        for (int i = 0; i < 8; i++) { S += ws[i]; Q += wq[i]; }
        float mu = S * (1.0f / 1024.0f);
        float var = Q * (1.0f / 1024.0f) - mu * mu;
        mu_s = mu;
        rstd_s = rsqrtf(var + 1e-5f);
    }
    __syncthreads();
    float mu = mu_s, rstd = rstd_s;
#pragma unroll
    for (int i = tid; i < 1024; i += 256) {
        out[(size_t)row * 1024 + i] = (yr[i] - mu) * rstd * gamma[i] + beta[i];
    }
}

// ---------------------------------------------------------------------------
extern "C" void kernel_launch(void* const* d_in, const int* in_sizes, int n_in,
                              void* d_out, int out_size)
{
    const float* x      = (const float*)d_in[0];
    // d_in[1] = market_info: softmax-invariant constant, unused
    const float* w_in   = (const float*)d_in[2];
    const float* b_in   = (const float*)d_in[3];
    const float* w_out  = (const float*)d_in[4];
    const float* b_out  = (const float*)d_in[5];
    const float* gamma  = (const float*)d_in[6];
    const float* beta   = (const float*)d_in[7];
    float* out = (float*)d_out;

    // fp32 -> fp16 prep (x, W_in, W_out)
    prep_kernel<<<(NQ_X + NQ_WI + NQ_WO) / 256, 256>>>(x, w_in, w_out);

    // GEMM smem: 2 buffers x (A + B) x 128 x 80 halves = 81920 B
    const int gemm_smem = 4 * 128 * GP * (int)sizeof(__half);
    cudaFuncSetAttribute(qkv_gemm, cudaFuncAttributeMaxDynamicSharedMemorySize, gemm_smem);
    cudaFuncSetAttribute(out_gemm, cudaFuncAttributeMaxDynamicSharedMemorySize, gemm_smem);

    // QKV projection
    qkv_gemm<<<dim3(24, 32), 128, gemm_smem>>>(b_in);

    // Attention: smem = (128 + 2*64 + 2*64) * 80 halves = 61440 B
    const int attn_smem = 384 * AP * (int)sizeof(__half);
    cudaFuncSetAttribute(attn_f16, cudaFuncAttributeMaxDynamicSharedMemorySize,
                         attn_smem);
    attn_f16<<<dim3(L_ / 128, B_ * H_), 128, attn_smem>>>();

    // Output projection + residual
    out_gemm<<<dim3(8, 32), 128, gemm_smem>>>(x, b_out);

    // LayerNorm
    ln_kernel<<<NT, 256>>>(gamma, beta, out);
}